// round 11
// baseline (speedup 1.0000x reference)
#include <cuda_runtime.h>
#include <cuda_bf16.h>
#include <cstdint>

#define NN   50000
#define EE   800000
#define FIN  128
#define DD   256
#define LL   3
#define GG   512
#define BN_EPS 1e-5f

// ======================= helpers ===========================================
__device__ __forceinline__ uint32_t smem_to_u32(const void* smem_ptr) {
    uint32_t addr;
    asm("{ .reg .u64 tmp; cvta.to.shared.u64 tmp, %1; cvt.u32.u64 %0, tmp; }"
        : "=r"(addr) : "l"(smem_ptr));
    return addr;
}
__device__ __forceinline__ void ldsm_x4(uint32_t* r, uint32_t addr) {
    asm volatile("ldmatrix.sync.aligned.m8n8.x4.shared.b16 {%0,%1,%2,%3}, [%4];"
        : "=r"(r[0]), "=r"(r[1]), "=r"(r[2]), "=r"(r[3]) : "r"(addr));
}
__device__ __forceinline__ void mma16816(float* d, const uint32_t* a,
                                         const uint32_t* b) {
    asm volatile(
        "mma.sync.aligned.m16n8k16.row.col.f32.bf16.bf16.f32 "
        "{%0,%1,%2,%3}, {%4,%5,%6,%7}, {%8,%9}, {%0,%1,%2,%3};"
        : "+f"(d[0]), "+f"(d[1]), "+f"(d[2]), "+f"(d[3])
        : "r"(a[0]), "r"(a[1]), "r"(a[2]), "r"(a[3]), "r"(b[0]), "r"(b[1]));
}
__device__ __forceinline__ void split2(float x, float y, uint32_t& h, uint32_t& l) {
    __nv_bfloat16 hx = __float2bfloat16(x), hy = __float2bfloat16(y);
    __nv_bfloat16 lx = __float2bfloat16(x - __bfloat162float(hx));
    __nv_bfloat16 ly = __float2bfloat16(y - __bfloat162float(hy));
    __nv_bfloat162 hh = __halves2bfloat162(hx, hy);
    __nv_bfloat162 ll = __halves2bfloat162(lx, ly);
    h = *reinterpret_cast<uint32_t*>(&hh);
    l = *reinterpret_cast<uint32_t*>(&ll);
}
__device__ __forceinline__ void red_add_v4(float* p, float4 v) {
    asm volatile("red.global.add.v4.f32 [%0], {%1,%2,%3,%4};"
                 :: "l"(p), "f"(v.x), "f"(v.y), "f"(v.z), "f"(v.w)
                 : "memory");
}
__device__ __forceinline__ void cpa16(uint32_t saddr, const void* g) {
    asm volatile("cp.async.cg.shared.global [%0], [%1], 16;"
                 :: "r"(saddr), "l"(g));
}
#define CPA_COMMIT() asm volatile("cp.async.commit_group;" ::: "memory")
#define CPA_WAIT0()  asm volatile("cp.async.wait_group 0;" ::: "memory")
#define CIDX(row, c8) ((row) * 4 + ((c8) ^ ((row) & 3)))

// ======================= scratch (device globals) ===========================
__device__ __align__(256) float g_h[(size_t)NN * DD];
__device__ __align__(256) float g_z[(size_t)NN * DD];
__device__ __align__(256) float g_t[(size_t)NN * DD];
__device__ __align__(256) float g_colsum[DD];
__device__ __align__(256) float g_colsq[DD];
__device__ __align__(256) float g_scale[DD];
__device__ __align__(256) float g_shift[DD];
__device__ __align__(256) float g_pooled[(size_t)GG * DD * LL];
__device__ __align__(256) float g_cnt[GG];
__device__ __align__(256) float g_hid[(size_t)GG * (DD / 2)];
__device__ __align__(256) __nv_bfloat16 g_Bhi[7 * 65536];
__device__ __align__(256) __nv_bfloat16 g_Blo[7 * 65536];
// CSR (dst-major)
__device__ __align__(256) int g_deg[NN];
__device__ __align__(256) int g_fill[NN];
__device__ __align__(256) int g_rowptr[NN + 1];
__device__ __align__(256) int g_colidx[EE];

// ======================= weight prep (all slots, one launch) ================
__global__ void prep_all_weights_kernel(const float* __restrict__ W_enc,
                                        const float* __restrict__ W1,
                                        const float* __restrict__ W2) {
    int idx = blockIdx.x * blockDim.x + threadIdx.x;
    const float* W;
    int slot, rel;
    if (idx < FIN * 256) {
        W = W_enc; slot = 0; rel = idx;
    } else {
        int idx2 = idx - FIN * 256;
        if (idx2 >= 6 * DD * 256) return;
        int q = idx2 / (DD * 256);
        rel = idx2 - q * (DD * 256);
        if (q < 3) { W = W1 + (size_t)q * DD * DD;       slot = 1 + q; }
        else       { W = W2 + (size_t)(q - 3) * DD * DD; slot = 1 + q; }
    }
    int kk = rel >> 8;
    int n  = rel & 255;
    float w = W[rel];
    __nv_bfloat16 hi = __float2bfloat16(w);
    __nv_bfloat16 lo = __float2bfloat16(w - __bfloat162float(hi));
    int nblk = n >> 7, nr = n & 127;
    int kchunk = kk >> 5, kc = kk & 31;
    int c8 = kc >> 3, w8 = kc & 7;
    size_t off = (size_t)slot * 65536 + ((size_t)nblk * 8 + kchunk) * 4096
               + (size_t)CIDX(nr, c8) * 8 + w8;
    g_Bhi[off] = hi;
    g_Blo[off] = lo;
}

// ======================= setup / CSR build ==================================
__global__ void zero_setup_kernel() {
    int i = blockIdx.x * blockDim.x + threadIdx.x;
    if (i < GG * DD * LL) g_pooled[i] = 0.f;
    if (i < GG)           g_cnt[i]    = 0.f;
    if (i < DD) { g_colsum[i] = 0.f; g_colsq[i] = 0.f; }
    if (i < NN) { g_deg[i] = 0; g_fill[i] = 0; }
}

__global__ void hist_count_kernel(const int* __restrict__ ei,
                                  const int* __restrict__ batch) {
    int e = blockIdx.x * blockDim.x + threadIdx.x;
    if (e < EE) atomicAdd(&g_deg[ei[EE + e]], 1);
    if (e < NN) atomicAdd(&g_cnt[batch[e]], 1.0f);
}

__global__ __launch_bounds__(1024)
void scan_kernel() {
    __shared__ int part[1024];
    const int t = threadIdx.x;
    const int per = (NN + 1023) / 1024;
    const int base = t * per;
    int s = 0;
    for (int i = 0; i < per; i++) {
        int idx = base + i;
        if (idx < NN) s += g_deg[idx];
    }
    part[t] = s;
    __syncthreads();
    for (int off = 1; off < 1024; off <<= 1) {
        int v = part[t];
        int u = (t >= off) ? part[t - off] : 0;
        __syncthreads();
        part[t] = v + u;
        __syncthreads();
    }
    int pre = (t > 0) ? part[t - 1] : 0;
    for (int i = 0; i < per; i++) {
        int idx = base + i;
        if (idx < NN) {
            int d = g_deg[idx];
            g_rowptr[idx] = pre;
            pre += d;
        }
    }
    if (t == 1023) g_rowptr[NN] = pre;
}

__global__ void fill_kernel(const int* __restrict__ ei) {
    int e = blockIdx.x * blockDim.x + threadIdx.x;
    if (e >= EE) return;
    int d = ei[EE + e];
    int pos = atomicAdd(&g_fill[d], 1);
    g_colidx[g_rowptr[d] + pos] = ei[e];
}

// ======================= gather: z[i] = h[i] + sum h[nbr] (unroll-4) ========
__global__ __launch_bounds__(256)
void gather_kernel() {
    const int wid  = threadIdx.x >> 5;
    const int lane = threadIdx.x & 31;
    const int row  = blockIdx.x * 8 + wid;
    if (row >= NN) return;
    const float4* base = (const float4*)g_h;
    const size_t rb = (size_t)row * 64;
    float4 a0 = base[rb + lane];
    float4 a1 = base[rb + 32 + lane];
    int e  = g_rowptr[row];
    const int e1 = g_rowptr[row + 1];
    for (; e + 4 <= e1; e += 4) {
        int s0 = g_colidx[e];
        int s1 = g_colidx[e + 1];
        int s2 = g_colidx[e + 2];
        int s3 = g_colidx[e + 3];
        float4 p0 = __ldg(&base[(size_t)s0 * 64 + lane]);
        float4 q0 = __ldg(&base[(size_t)s0 * 64 + 32 + lane]);
        float4 p1 = __ldg(&base[(size_t)s1 * 64 + lane]);
        float4 q1 = __ldg(&base[(size_t)s1 * 64 + 32 + lane]);
        float4 p2 = __ldg(&base[(size_t)s2 * 64 + lane]);
        float4 q2 = __ldg(&base[(size_t)s2 * 64 + 32 + lane]);
        float4 p3 = __ldg(&base[(size_t)s3 * 64 + lane]);
        float4 q3 = __ldg(&base[(size_t)s3 * 64 + 32 + lane]);
        p0.x += p1.x; p0.y += p1.y; p0.z += p1.z; p0.w += p1.w;
        p2.x += p3.x; p2.y += p3.y; p2.z += p3.z; p2.w += p3.w;
        q0.x += q1.x; q0.y += q1.y; q0.z += q1.z; q0.w += q1.w;
        q2.x += q3.x; q2.y += q3.y; q2.z += q3.z; q2.w += q3.w;
        a0.x += p0.x + p2.x; a0.y += p0.y + p2.y;
        a0.z += p0.z + p2.z; a0.w += p0.w + p2.w;
        a1.x += q0.x + q2.x; a1.y += q0.y + q2.y;
        a1.z += q0.z + q2.z; a1.w += q0.w + q2.w;
    }
    for (; e < e1; e++) {
        int s = g_colidx[e];
        float4 v0 = __ldg(&base[(size_t)s * 64 + lane]);
        float4 v1 = __ldg(&base[(size_t)s * 64 + 32 + lane]);
        a0.x += v0.x; a0.y += v0.y; a0.z += v0.z; a0.w += v0.w;
        a1.x += v1.x; a1.y += v1.y; a1.z += v1.z; a1.w += v1.w;
    }
    float4* zp = (float4*)g_z + rb;
    zp[lane]      = a0;
    zp[lane + 32] = a1;
}

// ======================= split-bf16 mma.sync GEMM ===========================
// Fully double-buffered (A and B), ONE __syncthreads per chunk.
// dynamic smem (65536B): sAhi 2x8K [0,16K)  sAlo 2x8K [16K,32K)
//                        sBhi 2x8K [32K,48K) sBlo 2x8K [48K,64K)
template <int RELU, int STATS>
__global__ __launch_bounds__(256, 2)
void mma_gemm_kernel(const float* __restrict__ A, int K, int slot,
                     const float* __restrict__ bias,
                     float* __restrict__ C, int M) {
    extern __shared__ char dsm[];
    uint4* sAhiB[2] = { (uint4*)dsm,            (uint4*)(dsm + 8192)  };
    uint4* sAloB[2] = { (uint4*)(dsm + 16384),  (uint4*)(dsm + 24576) };
    __shared__ float scs[128], scq[128];

    const int tid  = threadIdx.x;
    const int wid  = tid >> 5, lane = tid & 31;
    const int bm   = blockIdx.y * 128;
    const int bn   = blockIdx.x * 128;
    const int wm   = (wid & 3) * 32;
    const int wn   = (wid >> 2) * 64;
    const int nChunks = K >> 5;

    if (STATS) {
        if (tid < 128) { scs[tid] = 0.f; scq[tid] = 0.f; }
    }

    const uint32_t sb = smem_to_u32(dsm);
    const uint32_t aHiA[2] = { sb,          sb + 8192  };
    const uint32_t aLoA[2] = { sb + 16384,  sb + 24576 };
    const uint32_t bHiA[2] = { sb + 32768,  sb + 40960 };
    const uint32_t bLoA[2] = { sb + 49152,  sb + 57344 };

    int arow[2];
    arow[0] = wm + (lane & 15);
    arow[1] = wm + 16 + (lane & 15);
    const int ac8 = lane >> 4;
    int brow[4];
#pragma unroll
    for (int nt2 = 0; nt2 < 4; nt2++)
        brow[nt2] = wn + nt2 * 16 + (lane >> 4) * 8 + (lane & 7);
    const int bc8 = (lane >> 3) & 1;

    const int lrow = tid >> 1;
    const int lcsel = tid & 1;
    const bool lok = (bm + lrow) < M;
    const float* ap = A + (size_t)(bm + lrow) * K + lcsel * 16;

    float acc[2][8][4];
#pragma unroll
    for (int mt = 0; mt < 2; mt++)
#pragma unroll
        for (int nt = 0; nt < 8; nt++)
#pragma unroll
            for (int i = 0; i < 4; i++) acc[mt][nt][i] = 0.f;

    const uint4* bsrc_hi = (const uint4*)(g_Bhi + (size_t)slot * 65536
                                          + (size_t)blockIdx.x * 8 * 4096);
    const uint4* bsrc_lo = (const uint4*)(g_Blo + (size_t)slot * 65536
                                          + (size_t)blockIdx.x * 8 * 4096);

    // A-regs prefetch helper (clamped chunk index keeps loads in-bounds)
    float4 pre0, pre1, pre2, pre3;
#define LOAD_A_REGS(cc)                                                        \
    do {                                                                       \
        int _c = (cc) < nChunks ? (cc) : nChunks - 1;                          \
        const float* apc = ap + _c * 32;                                       \
        pre0 = lok ? *(const float4*)(apc + 0)  : make_float4(0.f,0.f,0.f,0.f);\
        pre1 = lok ? *(const float4*)(apc + 4)  : make_float4(0.f,0.f,0.f,0.f);\
        pre2 = lok ? *(const float4*)(apc + 8)  : make_float4(0.f,0.f,0.f,0.f);\
        pre3 = lok ? *(const float4*)(apc + 12) : make_float4(0.f,0.f,0.f,0.f);\
    } while (0)

#define STORE_A_SPLIT(buf)                                                     \
    do {                                                                       \
        uint4 h, l;                                                            \
        split2(pre0.x, pre0.y, h.x, l.x);                                      \
        split2(pre0.z, pre0.w, h.y, l.y);                                      \
        split2(pre1.x, pre1.y, h.z, l.z);                                      \
        split2(pre1.z, pre1.w, h.w, l.w);                                      \
        int ci = CIDX(lrow, lcsel * 2);                                        \
        sAhiB[buf][ci] = h; sAloB[buf][ci] = l;                                \
        split2(pre2.x, pre2.y, h.x, l.x);                                      \
        split2(pre2.z, pre2.w, h.y, l.y);                                      \
        split2(pre3.x, pre3.y, h.z, l.z);                                      \
        split2(pre3.z, pre3.w, h.w, l.w);                                      \
        ci = CIDX(lrow, lcsel * 2 + 1);                                        \
        sAhiB[buf][ci] = h; sAloB[buf][ci] = l;                                \
    } while (0)

    // prologue: A(0) -> buf0; regs <- A(1); cp.async B(0) -> buf0
    LOAD_A_REGS(0);
    STORE_A_SPLIT(0);
    LOAD_A_REGS(1);
    {
        cpa16(bHiA[0] + tid * 16,                bsrc_hi + tid);
        cpa16(bHiA[0] + tid * 16 + 4096,         bsrc_hi + tid + 256);
        cpa16(bLoA[0] + tid * 16,                bsrc_lo + tid);
        cpa16(bLoA[0] + tid * 16 + 4096,         bsrc_lo + tid + 256);
        CPA_COMMIT();
    }

    for (int c = 0; c < nChunks; c++) {
        const int par = c & 1;
        const int np  = par ^ 1;
        CPA_WAIT0();        // B(c) landed
        __syncthreads();    // A(c) stores visible; MMA(c-1) done with buffers np

        if (c + 1 < nChunks) {
            const uint4* sh = bsrc_hi + (size_t)(c + 1) * 512;
            const uint4* sl = bsrc_lo + (size_t)(c + 1) * 512;
            cpa16(bHiA[np] + tid * 16,        sh + tid);
            cpa16(bHiA[np] + tid * 16 + 4096, sh + tid + 256);
            cpa16(bLoA[np] + tid * 16,        sl + tid);
            cpa16(bLoA[np] + tid * 16 + 4096, sl + tid + 256);
            CPA_COMMIT();
            STORE_A_SPLIT(np);       // regs hold A(c+1)
            LOAD_A_REGS(c + 2);      // hide LDG under MMA(c)
        } else {
            CPA_COMMIT();
        }

        // MMA on chunk c
#pragma unroll
        for (int kk2 = 0; kk2 < 2; kk2++) {
            uint32_t Ah[2][4], Al[2][4], Bh[4][4], Bl[4][4];
#pragma unroll
            for (int mt = 0; mt < 2; mt++) {
                int ci = CIDX(arow[mt], kk2 * 2 + ac8);
                ldsm_x4(Ah[mt], aHiA[par] + ci * 16);
                ldsm_x4(Al[mt], aLoA[par] + ci * 16);
            }
#pragma unroll
            for (int nt2 = 0; nt2 < 4; nt2++) {
                int ci = CIDX(brow[nt2], kk2 * 2 + bc8);
                ldsm_x4(Bh[nt2], bHiA[par] + ci * 16);
                ldsm_x4(Bl[nt2], bLoA[par] + ci * 16);
            }
#pragma unroll
            for (int mt = 0; mt < 2; mt++)
#pragma unroll
                for (int nt = 0; nt < 8; nt++) {
                    const uint32_t* ph = &Bh[nt >> 1][(nt & 1) * 2];
                    const uint32_t* pl = &Bl[nt >> 1][(nt & 1) * 2];
                    mma16816(acc[mt][nt], Ah[mt], ph);
                    mma16816(acc[mt][nt], Ah[mt], pl);
                    mma16816(acc[mt][nt], Al[mt], ph);
                }
        }
    }
#undef LOAD_A_REGS
#undef STORE_A_SPLIT

    // ---- epilogue ----
    const int col0 = bn + wn + (lane & 3) * 2;
    float2 bv[8];
#pragma unroll
    for (int nt = 0; nt < 8; nt++)
        bv[nt] = *(const float2*)&bias[col0 + nt * 8];

    float s_c[8][2], q_c[8][2];
    if (STATS) {
#pragma unroll
        for (int nt = 0; nt < 8; nt++) {
            s_c[nt][0] = s_c[nt][1] = 0.f;
            q_c[nt][0] = q_c[nt][1] = 0.f;
        }
    }

#pragma unroll
    for (int mt = 0; mt < 2; mt++) {
        int ra = bm + wm + mt * 16 + (lane >> 2);
#pragma unroll
        for (int half = 0; half < 2; half++) {
            int r = ra + half * 8;
            if (r < M) {
                size_t rowoff = (size_t)r * 256;
#pragma unroll
                for (int nt = 0; nt < 8; nt++) {
                    float2 o;
                    o.x = acc[mt][nt][half * 2 + 0] + bv[nt].x;
                    o.y = acc[mt][nt][half * 2 + 1] + bv[nt].y;
                    if (RELU) { o.x = fmaxf(o.x, 0.f); o.y = fmaxf(o.y, 0.f); }
                    if (STATS) {
                        s_c[nt][0] += o.x;          s_c[nt][1] += o.y;
                        q_c[nt][0] = fmaf(o.x, o.x, q_c[nt][0]);
                        q_c[nt][1] = fmaf(o.y, o.y, q_c[nt][1]);
                    }
                    *(float2*)&C[rowoff + col0 + nt * 8] = o;
                }
            }
        }
    }

    if (STATS) {
        const int cb = wn + (lane & 3) * 2;
#pragma unroll
        for (int nt = 0; nt < 8; nt++) {
            atomicAdd(&scs[cb + nt * 8],     s_c[nt][0]);
            atomicAdd(&scs[cb + nt * 8 + 1], s_c[nt][1]);
            atomicAdd(&scq[cb + nt * 8],     q_c[nt][0]);
            atomicAdd(&scq[cb + nt * 8 + 1], q_c[nt][1]);
        }
        __syncthreads();
        if (tid < 128) {
            atomicAdd(&g_colsum[bn + tid], scs[tid]);
            atomicAdd(&g_colsq[bn + tid],  scq[tid]);
        }
    }
}

// ======================= BN finalize (self-resetting) =======================
__global__ void finalize_stats_kernel(const float* __restrict__ gamma,
                                      const float* __restrict__ beta) {
    int c = threadIdx.x;
    float mean = g_colsum[c] * (1.0f / NN);
    float var  = g_colsq[c] * (1.0f / NN) - mean * mean;
    float sc   = gamma[c] * rsqrtf(var + BN_EPS);
    g_scale[c] = sc;
    g_shift[c] = beta[c] - mean * sc;
    g_colsum[c] = 0.f;
    g_colsq[c]  = 0.f;
}

// ======================= BN apply + ReLU + pool =============================
__global__ __launch_bounds__(256)
void bn_apply_kernel(const int* __restrict__ batch, int layer) {
    int row = blockIdx.x * 4 + (threadIdx.x >> 6);
    if (row >= NN) return;
    int c4 = (threadIdx.x & 63) * 4;
    float4 v  = *(const float4*)&g_z[(size_t)row * DD + c4];
    float4 sc = *(const float4*)&g_scale[c4];
    float4 sh = *(const float4*)&g_shift[c4];
    float4 o;
    o.x = fmaxf(fmaf(v.x, sc.x, sh.x), 0.f);
    o.y = fmaxf(fmaf(v.y, sc.y, sh.y), 0.f);
    o.z = fmaxf(fmaf(v.z, sc.z, sh.z), 0.f);
    o.w = fmaxf(fmaf(v.w, sc.w, sh.w), 0.f);
    *(float4*)&g_h[(size_t)row * DD + c4] = o;
    int gidx = batch[row];
    red_add_v4(&g_pooled[(size_t)gidx * (DD * LL) + layer * DD + c4], o);
}

// ======================= MLP head ===========================================
__global__ __launch_bounds__(128)
void fc1_kernel(const float* __restrict__ W, const float* __restrict__ b) {
    int row = blockIdx.x;
    int j   = threadIdx.x;
    __shared__ float sp[DD * LL];
    for (int k = j; k < DD * LL; k += 128)
        sp[k] = g_pooled[(size_t)row * (DD * LL) + k];
    __syncthreads();
    float inv = 1.0f / fmaxf(g_cnt[row], 1.0f);
    float s = 0.f;
#pragma unroll 8
    for (int k = 0; k < DD * LL; k++)
        s = fmaf(sp[k], W[(size_t)k * 128 + j], s);
    g_hid[(size_t)row * 128 + j] = fmaxf(fmaf(s, inv, b[j]), 0.f);
}

__global__ __launch_bounds__(128)
void fc2_kernel(const float* __restrict__ W, const float* __restrict__ b,
                float* __restrict__ out) {
    int row = blockIdx.x;
    int t   = threadIdx.x;
    float v = g_hid[(size_t)row * 128 + t] * W[t];
#pragma unroll
    for (int off = 16; off; off >>= 1)
        v += __shfl_down_sync(0xFFFFFFFFu, v, off);
    __shared__ float ws[4];
    if ((t & 31) == 0) ws[t >> 5] = v;
    __syncthreads();
    if (t == 0) out[row] = ws[0] + ws[1] + ws[2] + ws[3] + b[0];
}

// ======================= launch ============================================
extern "C" void kernel_launch(void* const* d_in, const int* in_sizes, int n_in,
                              void* d_out, int out_size) {
    const float* x     = (const float*)d_in[0];
    const int*   ei    = (const int*)d_in[1];
    const int*   batch = (const int*)d_in[2];
    int base = n_in - 12;
    const float* W_enc = (const float*)d_in[base + 0];
    const float* b_enc = (const float*)d_in[base + 1];
    const float* W1    = (const float*)d_in[base + 2];
    const float* b1    = (const float*)d_in[base + 3];
    const float* W2    = (const float*)d_in[base + 4];
    const float* b2    = (const float*)d_in[base + 5];
    const float* gamma = (const float*)d_in[base + 6];
    const float* beta  = (const float*)d_in[base + 7];
    const float* Wf1   = (const float*)d_in[base + 8];
    const float* bf1   = (const float*)d_in[base + 9];
    const float* Wf2   = (const float*)d_in[base + 10];
    const float* bf2   = (const float*)d_in[base + 11];
    float* out = (float*)d_out;

    float *ph = nullptr, *pz = nullptr, *pt = nullptr;
    cudaGetSymbolAddress((void**)&ph, g_h);
    cudaGetSymbolAddress((void**)&pz, g_z);
    cudaGetSymbolAddress((void**)&pt, g_t);

    const int SMB = 65536;
    cudaFuncSetAttribute(mma_gemm_kernel<0, 0>,
                         cudaFuncAttributeMaxDynamicSharedMemorySize, SMB);
    cudaFuncSetAttribute(mma_gemm_kernel<1, 0>,
                         cudaFuncAttributeMaxDynamicSharedMemorySize, SMB);
    cudaFuncSetAttribute(mma_gemm_kernel<0, 1>,
                         cudaFuncAttributeMaxDynamicSharedMemorySize, SMB);

    dim3 ge(2, (NN + 127) / 128);   // (nblk, 391)

    prep_all_weights_kernel<<<(FIN * 256 + 6 * DD * 256 + 255) / 256, 256>>>(
        W_enc, W1, W2);
    zero_setup_kernel<<<(GG * DD * LL + 255) / 256, 256>>>();
    hist_count_kernel<<<(EE + 255) / 256, 256>>>(ei, batch);
    mma_gemm_kernel<0, 0><<<ge, 256, SMB>>>(x, FIN, 0, b_enc, ph, NN);
    scan_kernel<<<1, 1024>>>();
    fill_kernel<<<(EE + 255) / 256, 256>>>(ei);

    for (int l = 0; l < LL; l++) {
        gather_kernel<<<(NN + 7) / 8, 256>>>();
        mma_gemm_kernel<1, 0><<<ge, 256, SMB>>>(pz, DD, 1 + l, b1 + l * DD, pt, NN);
        mma_gemm_kernel<0, 1><<<ge, 256, SMB>>>(pt, DD, 4 + l, b2 + l * DD, pz, NN);
        finalize_stats_kernel<<<1, DD>>>(gamma + l * DD, beta + l * DD);
        bn_apply_kernel<<<NN / 4, 256>>>(batch, l);
    }

    fc1_kernel<<<GG, 128>>>(Wf1, bf1);
    fc2_kernel<<<GG, 128>>>(Wf2, bf2, out);
    (void)in_sizes; (void)out_size;
}

// round 12
// speedup vs baseline: 1.1861x; 1.1861x over previous
#include <cuda_runtime.h>
#include <cuda_bf16.h>
#include <cstdint>

#define NN   50000
#define EE   800000
#define FIN  128
#define DD   256
#define LL   3
#define GG   512
#define NPAD 50048          // 391 * 128
#define BN_EPS 1e-5f

// ======================= helpers ===========================================
__device__ __forceinline__ uint32_t smem_to_u32(const void* smem_ptr) {
    uint32_t addr;
    asm("{ .reg .u64 tmp; cvta.to.shared.u64 tmp, %1; cvt.u32.u64 %0, tmp; }"
        : "=r"(addr) : "l"(smem_ptr));
    return addr;
}
__device__ __forceinline__ void ldsm_x4(uint32_t* r, uint32_t addr) {
    asm volatile("ldmatrix.sync.aligned.m8n8.x4.shared.b16 {%0,%1,%2,%3}, [%4];"
        : "=r"(r[0]), "=r"(r[1]), "=r"(r[2]), "=r"(r[3]) : "r"(addr));
}
__device__ __forceinline__ void mma16816(float* d, const uint32_t* a,
                                         const uint32_t* b) {
    asm volatile(
        "mma.sync.aligned.m16n8k16.row.col.f32.bf16.bf16.f32 "
        "{%0,%1,%2,%3}, {%4,%5,%6,%7}, {%8,%9}, {%0,%1,%2,%3};"
        : "+f"(d[0]), "+f"(d[1]), "+f"(d[2]), "+f"(d[3])
        : "r"(a[0]), "r"(a[1]), "r"(a[2]), "r"(a[3]), "r"(b[0]), "r"(b[1]));
}
__device__ __forceinline__ void split2(float x, float y, uint32_t& h, uint32_t& l) {
    __nv_bfloat16 hx = __float2bfloat16(x), hy = __float2bfloat16(y);
    __nv_bfloat16 lx = __float2bfloat16(x - __bfloat162float(hx));
    __nv_bfloat16 ly = __float2bfloat16(y - __bfloat162float(hy));
    __nv_bfloat162 hh = __halves2bfloat162(hx, hy);
    __nv_bfloat162 ll = __halves2bfloat162(lx, ly);
    h = *reinterpret_cast<uint32_t*>(&hh);
    l = *reinterpret_cast<uint32_t*>(&ll);
}
__device__ __forceinline__ void red_add_v4(float* p, float4 v) {
    asm volatile("red.global.add.v4.f32 [%0], {%1,%2,%3,%4};"
                 :: "l"(p), "f"(v.x), "f"(v.y), "f"(v.z), "f"(v.w)
                 : "memory");
}
__device__ __forceinline__ void cpa16(uint32_t saddr, const void* g) {
    asm volatile("cp.async.cg.shared.global [%0], [%1], 16;"
                 :: "r"(saddr), "l"(g));
}
#define CPA_COMMIT() asm volatile("cp.async.commit_group;" ::: "memory")
#define CPA_WAIT0()  asm volatile("cp.async.wait_group 0;" ::: "memory")
#define CIDX(row, c8) ((row) * 4 + ((c8) ^ ((row) & 3)))

// ======================= scratch (device globals) ===========================
__device__ __align__(256) float g_h[(size_t)NN * DD];
__device__ __align__(256) float g_z[(size_t)NN * DD];
__device__ __align__(256) float g_colsum[DD];
__device__ __align__(256) float g_colsq[DD];
__device__ __align__(256) float g_scale[DD];
__device__ __align__(256) float g_shift[DD];
__device__ __align__(256) float g_pooled[(size_t)GG * DD * LL];
__device__ __align__(256) float g_cnt[GG];
__device__ __align__(256) float g_hid[(size_t)GG * (DD / 2)];
__device__ __align__(256) __nv_bfloat16 g_Bhi[7 * 65536];
__device__ __align__(256) __nv_bfloat16 g_Blo[7 * 65536];
// pre-split swizzled activations (A operands), tile layout [mb][kc][512x16B]
__device__ __align__(256) __nv_bfloat16 g_Ahi[(size_t)NPAD * DD];
__device__ __align__(256) __nv_bfloat16 g_Alo[(size_t)NPAD * DD];
__device__ __align__(256) __nv_bfloat16 g_Thi[(size_t)NPAD * DD];
__device__ __align__(256) __nv_bfloat16 g_Tlo[(size_t)NPAD * DD];
// CSR (dst-major)
__device__ __align__(256) int g_deg[NN];
__device__ __align__(256) int g_fill[NN];
__device__ __align__(256) int g_rowptr[NN + 1];
__device__ __align__(256) int g_colidx[EE];

// ======================= weight prep (all slots, one launch) ================
__global__ void prep_all_weights_kernel(const float* __restrict__ W_enc,
                                        const float* __restrict__ W1,
                                        const float* __restrict__ W2) {
    int idx = blockIdx.x * blockDim.x + threadIdx.x;
    const float* W;
    int slot, rel;
    if (idx < FIN * 256) {
        W = W_enc; slot = 0; rel = idx;
    } else {
        int idx2 = idx - FIN * 256;
        if (idx2 >= 6 * DD * 256) return;
        int q = idx2 / (DD * 256);
        rel = idx2 - q * (DD * 256);
        if (q < 3) { W = W1 + (size_t)q * DD * DD;       slot = 1 + q; }
        else       { W = W2 + (size_t)(q - 3) * DD * DD; slot = 1 + q; }
    }
    int kk = rel >> 8;
    int n  = rel & 255;
    float w = W[rel];
    __nv_bfloat16 hi = __float2bfloat16(w);
    __nv_bfloat16 lo = __float2bfloat16(w - __bfloat162float(hi));
    int nblk = n >> 7, nr = n & 127;
    int kchunk = kk >> 5, kc = kk & 31;
    int c8 = kc >> 3, w8 = kc & 7;
    size_t off = (size_t)slot * 65536 + ((size_t)nblk * 8 + kchunk) * 4096
               + (size_t)CIDX(nr, c8) * 8 + w8;
    g_Bhi[off] = hi;
    g_Blo[off] = lo;
}

// ======================= setup / CSR build ==================================
__global__ void zero_setup_kernel() {
    int i = blockIdx.x * blockDim.x + threadIdx.x;
    if (i < GG * DD * LL) g_pooled[i] = 0.f;
    if (i < GG)           g_cnt[i]    = 0.f;
    if (i < DD) { g_colsum[i] = 0.f; g_colsq[i] = 0.f; }
    if (i < NN) { g_deg[i] = 0; g_fill[i] = 0; }
}

__global__ void hist_count_kernel(const int* __restrict__ ei,
                                  const int* __restrict__ batch) {
    int e = blockIdx.x * blockDim.x + threadIdx.x;
    if (e < EE) atomicAdd(&g_deg[ei[EE + e]], 1);
    if (e < NN) atomicAdd(&g_cnt[batch[e]], 1.0f);
}

__global__ __launch_bounds__(1024)
void scan_kernel() {
    __shared__ int part[1024];
    const int t = threadIdx.x;
    const int per = (NN + 1023) / 1024;
    const int base = t * per;
    int s = 0;
    for (int i = 0; i < per; i++) {
        int idx = base + i;
        if (idx < NN) s += g_deg[idx];
    }
    part[t] = s;
    __syncthreads();
    for (int off = 1; off < 1024; off <<= 1) {
        int v = part[t];
        int u = (t >= off) ? part[t - off] : 0;
        __syncthreads();
        part[t] = v + u;
        __syncthreads();
    }
    int pre = (t > 0) ? part[t - 1] : 0;
    for (int i = 0; i < per; i++) {
        int idx = base + i;
        if (idx < NN) {
            int d = g_deg[idx];
            g_rowptr[idx] = pre;
            pre += d;
        }
    }
    if (t == 1023) g_rowptr[NN] = pre;
}

__global__ void fill_kernel(const int* __restrict__ ei) {
    int e = blockIdx.x * blockDim.x + threadIdx.x;
    if (e >= EE) return;
    int d = ei[EE + e];
    int pos = atomicAdd(&g_fill[d], 1);
    g_colidx[g_rowptr[d] + pos] = ei[e];
}

// ======================= gather -> pre-split swizzled A =====================
// lane owns 8 contiguous cols c0 = lane*8; output chunk = one uint4 per array
__global__ __launch_bounds__(256)
void gather_kernel() {
    const int wid  = threadIdx.x >> 5;
    const int lane = threadIdx.x & 31;
    const int row  = blockIdx.x * 8 + wid;
    if (row >= NN) return;
    const int c0 = lane * 8;
    const float* hp = g_h + (size_t)row * DD + c0;
    float4 a0 = *(const float4*)hp;
    float4 a1 = *(const float4*)(hp + 4);
    int e  = g_rowptr[row];
    const int e1 = g_rowptr[row + 1];
    for (; e + 4 <= e1; e += 4) {
        int s0 = g_colidx[e];
        int s1 = g_colidx[e + 1];
        int s2 = g_colidx[e + 2];
        int s3 = g_colidx[e + 3];
        const float* n0 = g_h + (size_t)s0 * DD + c0;
        const float* n1 = g_h + (size_t)s1 * DD + c0;
        const float* n2 = g_h + (size_t)s2 * DD + c0;
        const float* n3 = g_h + (size_t)s3 * DD + c0;
        float4 p0 = *(const float4*)n0, q0 = *(const float4*)(n0 + 4);
        float4 p1 = *(const float4*)n1, q1 = *(const float4*)(n1 + 4);
        float4 p2 = *(const float4*)n2, q2 = *(const float4*)(n2 + 4);
        float4 p3 = *(const float4*)n3, q3 = *(const float4*)(n3 + 4);
        p0.x += p1.x; p0.y += p1.y; p0.z += p1.z; p0.w += p1.w;
        p2.x += p3.x; p2.y += p3.y; p2.z += p3.z; p2.w += p3.w;
        q0.x += q1.x; q0.y += q1.y; q0.z += q1.z; q0.w += q1.w;
        q2.x += q3.x; q2.y += q3.y; q2.z += q3.z; q2.w += q3.w;
        a0.x += p0.x + p2.x; a0.y += p0.y + p2.y;
        a0.z += p0.z + p2.z; a0.w += p0.w + p2.w;
        a1.x += q0.x + q2.x; a1.y += q0.y + q2.y;
        a1.z += q0.z + q2.z; a1.w += q0.w + q2.w;
    }
    for (; e < e1; e++) {
        int s = g_colidx[e];
        const float* n0 = g_h + (size_t)s * DD + c0;
        float4 v0 = *(const float4*)n0;
        float4 v1 = *(const float4*)(n0 + 4);
        a0.x += v0.x; a0.y += v0.y; a0.z += v0.z; a0.w += v0.w;
        a1.x += v1.x; a1.y += v1.y; a1.z += v1.z; a1.w += v1.w;
    }
    // split + swizzled store (one 16B chunk per array)
    uint4 h4, l4;
    split2(a0.x, a0.y, h4.x, l4.x);
    split2(a0.z, a0.w, h4.y, l4.y);
    split2(a1.x, a1.y, h4.z, l4.z);
    split2(a1.z, a1.w, h4.w, l4.w);
    int mb = row >> 7, rr = row & 127;
    size_t ch = ((size_t)mb * 8 + (lane >> 2)) * 512 + CIDX(rr, lane & 3);
    ((uint4*)g_Ahi)[ch] = h4;
    ((uint4*)g_Alo)[ch] = l4;
}

// ======================= GEMM (conv path, encoder only) — R10 proven ========
__global__ __launch_bounds__(256, 2)
void mma_gemm_conv(const float* __restrict__ A, int K, int slot,
                   const float* __restrict__ bias,
                   float* __restrict__ C, int M) {
    extern __shared__ char dsm[];
    uint4* sAhi = (uint4*)dsm;
    uint4* sAlo = (uint4*)(dsm + 8192);

    const int tid  = threadIdx.x;
    const int wid  = tid >> 5, lane = tid & 31;
    const int bm   = blockIdx.y * 128;
    const int bn   = blockIdx.x * 128;
    const int wm   = (wid & 3) * 32;
    const int wn   = (wid >> 2) * 64;
    const int nChunks = K >> 5;

    const uint32_t sb = smem_to_u32(dsm);
    const uint32_t aHi = sb;
    const uint32_t aLo = sb + 8192;
    const uint32_t bHiA[2] = { sb + 16384, sb + 24576 };
    const uint32_t bLoA[2] = { sb + 32768, sb + 40960 };

    int arow[2];
    arow[0] = wm + (lane & 15);
    arow[1] = wm + 16 + (lane & 15);
    const int ac8 = lane >> 4;
    int brow[4];
#pragma unroll
    for (int nt2 = 0; nt2 < 4; nt2++)
        brow[nt2] = wn + nt2 * 16 + (lane >> 4) * 8 + (lane & 7);
    const int bc8 = (lane >> 3) & 1;

    const int lrow = tid >> 1;
    const int lcsel = tid & 1;
    const bool lok = (bm + lrow) < M;
    const float* ap = A + (size_t)(bm + lrow) * K + lcsel * 16;

    float acc[2][8][4];
#pragma unroll
    for (int mt = 0; mt < 2; mt++)
#pragma unroll
        for (int nt = 0; nt < 8; nt++)
#pragma unroll
            for (int i = 0; i < 4; i++) acc[mt][nt][i] = 0.f;

    const uint4* bsrc_hi = (const uint4*)(g_Bhi + (size_t)slot * 65536
                                          + (size_t)blockIdx.x * 8 * 4096);
    const uint4* bsrc_lo = (const uint4*)(g_Blo + (size_t)slot * 65536
                                          + (size_t)blockIdx.x * 8 * 4096);

    float4 pre0, pre1, pre2, pre3;
    {
        const float* apc = ap;
        pre0 = lok ? *(const float4*)(apc + 0)  : make_float4(0.f, 0.f, 0.f, 0.f);
        pre1 = lok ? *(const float4*)(apc + 4)  : make_float4(0.f, 0.f, 0.f, 0.f);
        pre2 = lok ? *(const float4*)(apc + 8)  : make_float4(0.f, 0.f, 0.f, 0.f);
        pre3 = lok ? *(const float4*)(apc + 12) : make_float4(0.f, 0.f, 0.f, 0.f);
        cpa16(bHiA[0] + tid * 16,        bsrc_hi + tid);
        cpa16(bHiA[0] + tid * 16 + 4096, bsrc_hi + tid + 256);
        cpa16(bLoA[0] + tid * 16,        bsrc_lo + tid);
        cpa16(bLoA[0] + tid * 16 + 4096, bsrc_lo + tid + 256);
        CPA_COMMIT();
    }

    for (int c = 0; c < nChunks; c++) {
        const int par = c & 1;
        CPA_WAIT0();
        __syncthreads();

        {
            uint4 h, l;
            split2(pre0.x, pre0.y, h.x, l.x);
            split2(pre0.z, pre0.w, h.y, l.y);
            split2(pre1.x, pre1.y, h.z, l.z);
            split2(pre1.z, pre1.w, h.w, l.w);
            int ci = CIDX(lrow, lcsel * 2);
            sAhi[ci] = h; sAlo[ci] = l;
            split2(pre2.x, pre2.y, h.x, l.x);
            split2(pre2.z, pre2.w, h.y, l.y);
            split2(pre3.x, pre3.y, h.z, l.z);
            split2(pre3.z, pre3.w, h.w, l.w);
            ci = CIDX(lrow, lcsel * 2 + 1);
            sAhi[ci] = h; sAlo[ci] = l;
        }
        if (c + 1 < nChunks) {
            const int np = (c + 1) & 1;
            const uint4* sh = bsrc_hi + (size_t)(c + 1) * 512;
            const uint4* sl = bsrc_lo + (size_t)(c + 1) * 512;
            cpa16(bHiA[np] + tid * 16,        sh + tid);
            cpa16(bHiA[np] + tid * 16 + 4096, sh + tid + 256);
            cpa16(bLoA[np] + tid * 16,        sl + tid);
            cpa16(bLoA[np] + tid * 16 + 4096, sl + tid + 256);
            CPA_COMMIT();
            const float* apc = ap + (c + 1) * 32;
            pre0 = lok ? *(const float4*)(apc + 0)  : make_float4(0.f, 0.f, 0.f, 0.f);
            pre1 = lok ? *(const float4*)(apc + 4)  : make_float4(0.f, 0.f, 0.f, 0.f);
            pre2 = lok ? *(const float4*)(apc + 8)  : make_float4(0.f, 0.f, 0.f, 0.f);
            pre3 = lok ? *(const float4*)(apc + 12) : make_float4(0.f, 0.f, 0.f, 0.f);
        } else {
            CPA_COMMIT();
        }
        __syncthreads();

#pragma unroll
        for (int kk2 = 0; kk2 < 2; kk2++) {
            uint32_t Ah[2][4], Al[2][4], Bh[4][4], Bl[4][4];
#pragma unroll
            for (int mt = 0; mt < 2; mt++) {
                int ci = CIDX(arow[mt], kk2 * 2 + ac8);
                ldsm_x4(Ah[mt], aHi + ci * 16);
                ldsm_x4(Al[mt], aLo + ci * 16);
            }
#pragma unroll
            for (int nt2 = 0; nt2 < 4; nt2++) {
                int ci = CIDX(brow[nt2], kk2 * 2 + bc8);
                ldsm_x4(Bh[nt2], bHiA[par] + ci * 16);
                ldsm_x4(Bl[nt2], bLoA[par] + ci * 16);
            }
#pragma unroll
            for (int mt = 0; mt < 2; mt++)
#pragma unroll
                for (int nt = 0; nt < 8; nt++) {
                    const uint32_t* ph = &Bh[nt >> 1][(nt & 1) * 2];
                    const uint32_t* pl = &Bl[nt >> 1][(nt & 1) * 2];
                    mma16816(acc[mt][nt], Ah[mt], ph);
                    mma16816(acc[mt][nt], Ah[mt], pl);
                    mma16816(acc[mt][nt], Al[mt], ph);
                }
        }
    }

    // epilogue: plain fp32 C
    const int col0 = bn + wn + (lane & 3) * 2;
    float2 bv[8];
#pragma unroll
    for (int nt = 0; nt < 8; nt++)
        bv[nt] = *(const float2*)&bias[col0 + nt * 8];

#pragma unroll
    for (int mt = 0; mt < 2; mt++) {
        int ra = bm + wm + mt * 16 + (lane >> 2);
#pragma unroll
        for (int half = 0; half < 2; half++) {
            int r = ra + half * 8;
            if (r < M) {
                size_t rowoff = (size_t)r * 256;
#pragma unroll
                for (int nt = 0; nt < 8; nt++) {
                    float2 o;
                    o.x = acc[mt][nt][half * 2 + 0] + bv[nt].x;
                    o.y = acc[mt][nt][half * 2 + 1] + bv[nt].y;
                    *(float2*)&C[rowoff + col0 + nt * 8] = o;
                }
            }
        }
    }
}

// ======================= GEMM (pre-split A path) ============================
// A and B both cp.async double-buffered, one sync per chunk, no converts.
// smem 64KB: aHi 2x8K [0,16K) aLo [16K,32K) bHi [32K,48K) bLo [48K,64K)
template <int RELU, int STATS, int TSPLIT>
__global__ __launch_bounds__(256, 2)
void mma_gemm_pre(const __nv_bfloat16* __restrict__ Ahi,
                  const __nv_bfloat16* __restrict__ Alo,
                  int slot, const float* __restrict__ bias,
                  float* __restrict__ C,
                  __nv_bfloat16* __restrict__ Thi,
                  __nv_bfloat16* __restrict__ Tlo, int M) {
    extern __shared__ char dsm[];
    __shared__ float scs[128], scq[128];

    const int tid  = threadIdx.x;
    const int wid  = tid >> 5, lane = tid & 31;
    const int bm   = blockIdx.y * 128;
    const int bn   = blockIdx.x * 128;
    const int wm   = (wid & 3) * 32;
    const int wn   = (wid >> 2) * 64;
    const int nChunks = 8;   // K = 256

    if (STATS) {
        if (tid < 128) { scs[tid] = 0.f; scq[tid] = 0.f; }
    }

    const uint32_t sb = smem_to_u32(dsm);
    const uint32_t aHiA[2] = { sb,         sb + 8192  };
    const uint32_t aLoA[2] = { sb + 16384, sb + 24576 };
    const uint32_t bHiA[2] = { sb + 32768, sb + 40960 };
    const uint32_t bLoA[2] = { sb + 49152, sb + 57344 };

    int arow[2];
    arow[0] = wm + (lane & 15);
    arow[1] = wm + 16 + (lane & 15);
    const int ac8 = lane >> 4;
    int brow[4];
#pragma unroll
    for (int nt2 = 0; nt2 < 4; nt2++)
        brow[nt2] = wn + nt2 * 16 + (lane >> 4) * 8 + (lane & 7);
    const int bc8 = (lane >> 3) & 1;

    float acc[2][8][4];
#pragma unroll
    for (int mt = 0; mt < 2; mt++)
#pragma unroll
        for (int nt = 0; nt < 8; nt++)
#pragma unroll
            for (int i = 0; i < 4; i++) acc[mt][nt][i] = 0.f;

    const uint4* asrc_hi = (const uint4*)Ahi + (size_t)blockIdx.y * 4096;
    const uint4* asrc_lo = (const uint4*)Alo + (size_t)blockIdx.y * 4096;
    const uint4* bsrc_hi = (const uint4*)(g_Bhi + (size_t)slot * 65536
                                          + (size_t)blockIdx.x * 8 * 4096);
    const uint4* bsrc_lo = (const uint4*)(g_Blo + (size_t)slot * 65536
                                          + (size_t)blockIdx.x * 8 * 4096);

#define LOAD_CHUNK(cc, buf)                                                    \
    do {                                                                       \
        const uint4* ah = asrc_hi + (size_t)(cc) * 512;                        \
        const uint4* al = asrc_lo + (size_t)(cc) * 512;                        \
        const uint4* bh = bsrc_hi + (size_t)(cc) * 512;                        \
        const uint4* bl = bsrc_lo + (size_t)(cc) * 512;                        \
        cpa16(aHiA[buf] + tid * 16,        ah + tid);                          \
        cpa16(aHiA[buf] + tid * 16 + 4096, ah + tid + 256);                    \
        cpa16(aLoA[buf] + tid * 16,        al + tid);                          \
        cpa16(aLoA[buf] + tid * 16 + 4096, al + tid + 256);                    \
        cpa16(bHiA[buf] + tid * 16,        bh + tid);                          \
        cpa16(bHiA[buf] + tid * 16 + 4096, bh + tid + 256);                    \
        cpa16(bLoA[buf] + tid * 16,        bl + tid);                          \
        cpa16(bLoA[buf] + tid * 16 + 4096, bl + tid + 256);                    \
        CPA_COMMIT();                                                          \
    } while (0)

    LOAD_CHUNK(0, 0);

    for (int c = 0; c < nChunks; c++) {
        const int par = c & 1;
        const int np  = par ^ 1;
        CPA_WAIT0();
        __syncthreads();    // chunk c landed; MMA(c-1) done reading np

        if (c + 1 < nChunks) LOAD_CHUNK(c + 1, np);
        else CPA_COMMIT();

#pragma unroll
        for (int kk2 = 0; kk2 < 2; kk2++) {
            uint32_t Ah[2][4], Al[2][4], Bh[4][4], Bl[4][4];
#pragma unroll
            for (int mt = 0; mt < 2; mt++) {
                int ci = CIDX(arow[mt], kk2 * 2 + ac8);
                ldsm_x4(Ah[mt], aHiA[par] + ci * 16);
                ldsm_x4(Al[mt], aLoA[par] + ci * 16);
            }
#pragma unroll
            for (int nt2 = 0; nt2 < 4; nt2++) {
                int ci = CIDX(brow[nt2], kk2 * 2 + bc8);
                ldsm_x4(Bh[nt2], bHiA[par] + ci * 16);
                ldsm_x4(Bl[nt2], bLoA[par] + ci * 16);
            }
#pragma unroll
            for (int mt = 0; mt < 2; mt++)
#pragma unroll
                for (int nt = 0; nt < 8; nt++) {
                    const uint32_t* ph = &Bh[nt >> 1][(nt & 1) * 2];
                    const uint32_t* pl = &Bl[nt >> 1][(nt & 1) * 2];
                    mma16816(acc[mt][nt], Ah[mt], ph);
                    mma16816(acc[mt][nt], Ah[mt], pl);
                    mma16816(acc[mt][nt], Al[mt], ph);
                }
        }
    }
#undef LOAD_CHUNK

    // ---- epilogue ----
    const int col0 = bn + wn + (lane & 3) * 2;
    float2 bv[8];
#pragma unroll
    for (int nt = 0; nt < 8; nt++)
        bv[nt] = *(const float2*)&bias[col0 + nt * 8];

    float s_c[8][2], q_c[8][2];
    if (STATS) {
#pragma unroll
        for (int nt = 0; nt < 8; nt++) {
            s_c[nt][0] = s_c[nt][1] = 0.f;
            q_c[nt][0] = q_c[nt][1] = 0.f;
        }
    }

#pragma unroll
    for (int mt = 0; mt < 2; mt++) {
#pragma unroll
        for (int half = 0; half < 2; half++) {
            int rr = wm + mt * 16 + (lane >> 2) + half * 8;   // row within tile
            int r  = bm + rr;
            if (r < M) {
                size_t rowoff = (size_t)r * 256;
#pragma unroll
                for (int nt = 0; nt < 8; nt++) {
                    float2 o;
                    o.x = acc[mt][nt][half * 2 + 0] + bv[nt].x;
                    o.y = acc[mt][nt][half * 2 + 1] + bv[nt].y;
                    if (RELU) { o.x = fmaxf(o.x, 0.f); o.y = fmaxf(o.y, 0.f); }
                    if (STATS) {
                        s_c[nt][0] += o.x;          s_c[nt][1] += o.y;
                        q_c[nt][0] = fmaf(o.x, o.x, q_c[nt][0]);
                        q_c[nt][1] = fmaf(o.y, o.y, q_c[nt][1]);
                    }
                    if (TSPLIT) {
                        int colg = col0 + nt * 8;
                        int kc = colg >> 5;
                        int c8 = (colg >> 3) & 3;
                        size_t ch = ((size_t)blockIdx.y * 8 + kc) * 512
                                  + CIDX(rr, c8);
                        uint32_t hb, lb;
                        split2(o.x, o.y, hb, lb);
                        *(uint32_t*)((char*)Thi + ch * 16 + (lane & 3) * 4) = hb;
                        *(uint32_t*)((char*)Tlo + ch * 16 + (lane & 3) * 4) = lb;
                    } else {
                        *(float2*)&C[rowoff + col0 + nt * 8] = o;
                    }
                }
            }
        }
    }

    if (STATS) {
        const int cb = wn + (lane & 3) * 2;
#pragma unroll
        for (int nt = 0; nt < 8; nt++) {
            atomicAdd(&scs[cb + nt * 8],     s_c[nt][0]);
            atomicAdd(&scs[cb + nt * 8 + 1], s_c[nt][1]);
            atomicAdd(&scq[cb + nt * 8],     q_c[nt][0]);
            atomicAdd(&scq[cb + nt * 8 + 1], q_c[nt][1]);
        }
        __syncthreads();
        if (tid < 128) {
            atomicAdd(&g_colsum[bn + tid], scs[tid]);
            atomicAdd(&g_colsq[bn + tid],  scq[tid]);
        }
    }
}

// ======================= BN finalize (self-resetting) =======================
__global__ void finalize_stats_kernel(const float* __restrict__ gamma,
                                      const float* __restrict__ beta) {
    int c = threadIdx.x;
    float mean = g_colsum[c] * (1.0f / NN);
    float var  = g_colsq[c] * (1.0f / NN) - mean * mean;
    float sc   = gamma[c] * rsqrtf(var + BN_EPS);
    g_scale[c] = sc;
    g_shift[c] = beta[c] - mean * sc;
    g_colsum[c] = 0.f;
    g_colsq[c]  = 0.f;
}

// ======================= BN apply + ReLU + pool =============================
__global__ __launch_bounds__(256)
void bn_apply_kernel(const int* __restrict__ batch, int layer) {
    int row = blockIdx.x * 4 + (threadIdx.x >> 6);
    if (row >= NN) return;
    int c4 = (threadIdx.x & 63) * 4;
    float4 v  = *(const float4*)&g_z[(size_t)row * DD + c4];
    float4 sc = *(const float4*)&g_scale[c4];
    float4 sh = *(const float4*)&g_shift[c4];
    float4 o;
    o.x = fmaxf(fmaf(v.x, sc.x, sh.x), 0.f);
    o.y = fmaxf(fmaf(v.y, sc.y, sh.y), 0.f);
    o.z = fmaxf(fmaf(v.z, sc.z, sh.z), 0.f);
    o.w = fmaxf(fmaf(v.w, sc.w, sh.w), 0.f);
    *(float4*)&g_h[(size_t)row * DD + c4] = o;
    int gidx = batch[row];
    red_add_v4(&g_pooled[(size_t)gidx * (DD * LL) + layer * DD + c4], o);
}

// ======================= MLP head ===========================================
__global__ __launch_bounds__(128)
void fc1_kernel(const float* __restrict__ W, const float* __restrict__ b) {
    int row = blockIdx.x;
    int j   = threadIdx.x;
    __shared__ float sp[DD * LL];
    for (int k = j; k < DD * LL; k += 128)
        sp[k] = g_pooled[(size_t)row * (DD * LL) + k];
    __syncthreads();
    float inv = 1.0f / fmaxf(g_cnt[row], 1.0f);
    float s = 0.f;
#pragma unroll 8
    for (int k = 0; k < DD * LL; k++)
        s = fmaf(sp[k], W[(size_t)k * 128 + j], s);
    g_hid[(size_t)row * 128 + j] = fmaxf(fmaf(s, inv, b[j]), 0.f);
}

__global__ __launch_bounds__(128)
void fc2_kernel(const float* __restrict__ W, const float* __restrict__ b,
                float* __restrict__ out) {
    int row = blockIdx.x;
    int t   = threadIdx.x;
    float v = g_hid[(size_t)row * 128 + t] * W[t];
#pragma unroll
    for (int off = 16; off; off >>= 1)
        v += __shfl_down_sync(0xFFFFFFFFu, v, off);
    __shared__ float ws[4];
    if ((t & 31) == 0) ws[t >> 5] = v;
    __syncthreads();
    if (t == 0) out[row] = ws[0] + ws[1] + ws[2] + ws[3] + b[0];
}

// ======================= launch ============================================
extern "C" void kernel_launch(void* const* d_in, const int* in_sizes, int n_in,
                              void* d_out, int out_size) {
    const float* x     = (const float*)d_in[0];
    const int*   ei    = (const int*)d_in[1];
    const int*   batch = (const int*)d_in[2];
    int base = n_in - 12;
    const float* W_enc = (const float*)d_in[base + 0];
    const float* b_enc = (const float*)d_in[base + 1];
    const float* W1    = (const float*)d_in[base + 2];
    const float* b1    = (const float*)d_in[base + 3];
    const float* W2    = (const float*)d_in[base + 4];
    const float* b2    = (const float*)d_in[base + 5];
    const float* gamma = (const float*)d_in[base + 6];
    const float* beta  = (const float*)d_in[base + 7];
    const float* Wf1   = (const float*)d_in[base + 8];
    const float* bf1   = (const float*)d_in[base + 9];
    const float* Wf2   = (const float*)d_in[base + 10];
    const float* bf2   = (const float*)d_in[base + 11];
    float* out = (float*)d_out;

    float *ph = nullptr, *pz = nullptr;
    __nv_bfloat16 *pAhi = nullptr, *pAlo = nullptr, *pThi = nullptr, *pTlo = nullptr;
    cudaGetSymbolAddress((void**)&ph, g_h);
    cudaGetSymbolAddress((void**)&pz, g_z);
    cudaGetSymbolAddress((void**)&pAhi, g_Ahi);
    cudaGetSymbolAddress((void**)&pAlo, g_Alo);
    cudaGetSymbolAddress((void**)&pThi, g_Thi);
    cudaGetSymbolAddress((void**)&pTlo, g_Tlo);

    const int SMB_CONV = 49152;
    const int SMB_PRE  = 65536;
    cudaFuncSetAttribute(mma_gemm_conv,
                         cudaFuncAttributeMaxDynamicSharedMemorySize, SMB_CONV);
    cudaFuncSetAttribute(mma_gemm_pre<1, 0, 1>,
                         cudaFuncAttributeMaxDynamicSharedMemorySize, SMB_PRE);
    cudaFuncSetAttribute(mma_gemm_pre<0, 1, 0>,
                         cudaFuncAttributeMaxDynamicSharedMemorySize, SMB_PRE);

    dim3 ge(2, (NN + 127) / 128);   // (nblk, 391)

    prep_all_weights_kernel<<<(FIN * 256 + 6 * DD * 256 + 255) / 256, 256>>>(
        W_enc, W1, W2);
    zero_setup_kernel<<<(GG * DD * LL + 255) / 256, 256>>>();
    hist_count_kernel<<<(EE + 255) / 256, 256>>>(ei, batch);
    mma_gemm_conv<<<ge, 256, SMB_CONV>>>(x, FIN, 0, b_enc, ph, NN);
    scan_kernel<<<1, 1024>>>();
    fill_kernel<<<(EE + 255) / 256, 256>>>(ei);

    for (int l = 0; l < LL; l++) {
        gather_kernel<<<(NN + 7) / 8, 256>>>();   // g_h -> g_Ahi/g_Alo (split)
        mma_gemm_pre<1, 0, 1><<<ge, 256, SMB_PRE>>>(
            pAhi, pAlo, 1 + l, b1 + l * DD, pz, pThi, pTlo, NN);   // t (split)
        mma_gemm_pre<0, 1, 0><<<ge, 256, SMB_PRE>>>(
            pThi, pTlo, 4 + l, b2 + l * DD, pz, pThi, pTlo, NN);   // z + stats
        finalize_stats_kernel<<<1, DD>>>(gamma + l * DD, beta + l * DD);
        bn_apply_kernel<<<NN / 4, 256>>>(batch, l);
    }

    fc1_kernel<<<GG, 128>>>(Wf1, bf1);
    fc2_kernel<<<GG, 128>>>(Wf2, bf2, out);
    (void)in_sizes; (void)out_size;
}

// round 13
// speedup vs baseline: 1.2345x; 1.0408x over previous
#include <cuda_runtime.h>
#include <cuda_bf16.h>
#include <cuda_fp16.h>
#include <cstdint>

#define NN   50000
#define EE   800000
#define FIN  128
#define DD   256
#define LL   3
#define GG   512
#define NPAD 50048          // 391 * 128
#define BN_EPS 1e-5f

// ======================= helpers ===========================================
__device__ __forceinline__ uint32_t smem_to_u32(const void* smem_ptr) {
    uint32_t addr;
    asm("{ .reg .u64 tmp; cvta.to.shared.u64 tmp, %1; cvt.u32.u64 %0, tmp; }"
        : "=r"(addr) : "l"(smem_ptr));
    return addr;
}
__device__ __forceinline__ void ldsm_x4(uint32_t* r, uint32_t addr) {
    asm volatile("ldmatrix.sync.aligned.m8n8.x4.shared.b16 {%0,%1,%2,%3}, [%4];"
        : "=r"(r[0]), "=r"(r[1]), "=r"(r[2]), "=r"(r[3]) : "r"(addr));
}
__device__ __forceinline__ void mma16816(float* d, const uint32_t* a,
                                         const uint32_t* b) {
    asm volatile(
        "mma.sync.aligned.m16n8k16.row.col.f32.bf16.bf16.f32 "
        "{%0,%1,%2,%3}, {%4,%5,%6,%7}, {%8,%9}, {%0,%1,%2,%3};"
        : "+f"(d[0]), "+f"(d[1]), "+f"(d[2]), "+f"(d[3])
        : "r"(a[0]), "r"(a[1]), "r"(a[2]), "r"(a[3]), "r"(b[0]), "r"(b[1]));
}
__device__ __forceinline__ void split2(float x, float y, uint32_t& h, uint32_t& l) {
    __nv_bfloat16 hx = __float2bfloat16(x), hy = __float2bfloat16(y);
    __nv_bfloat16 lx = __float2bfloat16(x - __bfloat162float(hx));
    __nv_bfloat16 ly = __float2bfloat16(y - __bfloat162float(hy));
    __nv_bfloat162 hh = __halves2bfloat162(hx, hy);
    __nv_bfloat162 ll = __halves2bfloat162(lx, ly);
    h = *reinterpret_cast<uint32_t*>(&hh);
    l = *reinterpret_cast<uint32_t*>(&ll);
}
__device__ __forceinline__ void red_add_v4(float* p, float4 v) {
    asm volatile("red.global.add.v4.f32 [%0], {%1,%2,%3,%4};"
                 :: "l"(p), "f"(v.x), "f"(v.y), "f"(v.z), "f"(v.w)
                 : "memory");
}
__device__ __forceinline__ void cpa16(uint32_t saddr, const void* g) {
    asm volatile("cp.async.cg.shared.global [%0], [%1], 16;"
                 :: "r"(saddr), "l"(g));
}
#define CPA_COMMIT() asm volatile("cp.async.commit_group;" ::: "memory")
#define CPA_WAIT0()  asm volatile("cp.async.wait_group 0;" ::: "memory")
#define CIDX(row, c8) ((row) * 4 + ((c8) ^ ((row) & 3)))

// ======================= scratch (device globals) ===========================
__device__ __align__(256) float  g_h[(size_t)NN * DD];
__device__ __align__(256) __half g_hb[(size_t)NN * DD];   // fp16 neighbor cache
__device__ __align__(256) float  g_z[(size_t)NN * DD];
__device__ __align__(256) float  g_colsum[DD];
__device__ __align__(256) float  g_colsq[DD];
__device__ __align__(256) float  g_scale[DD];
__device__ __align__(256) float  g_shift[DD];
__device__ __align__(256) float  g_pooled[(size_t)GG * DD * LL];
__device__ __align__(256) float  g_cnt[GG];
__device__ __align__(256) float  g_hid[(size_t)GG * (DD / 2)];
__device__ __align__(256) __nv_bfloat16 g_Bhi[7 * 65536];
__device__ __align__(256) __nv_bfloat16 g_Blo[7 * 65536];
// pre-split swizzled activations (A operands), tile layout [mb][kc][512x16B]
__device__ __align__(256) __nv_bfloat16 g_Ahi[(size_t)NPAD * DD];
__device__ __align__(256) __nv_bfloat16 g_Alo[(size_t)NPAD * DD];
__device__ __align__(256) __nv_bfloat16 g_Thi[(size_t)NPAD * DD];
__device__ __align__(256) __nv_bfloat16 g_Tlo[(size_t)NPAD * DD];
// CSR (dst-major)
__device__ __align__(256) int g_deg[NN];
__device__ __align__(256) int g_fill[NN];
__device__ __align__(256) int g_rowptr[NN + 1];
__device__ __align__(256) int g_colidx[EE];

// ======================= weight prep (all slots, one launch) ================
__global__ void prep_all_weights_kernel(const float* __restrict__ W_enc,
                                        const float* __restrict__ W1,
                                        const float* __restrict__ W2) {
    int idx = blockIdx.x * blockDim.x + threadIdx.x;
    const float* W;
    int slot, rel;
    if (idx < FIN * 256) {
        W = W_enc; slot = 0; rel = idx;
    } else {
        int idx2 = idx - FIN * 256;
        if (idx2 >= 6 * DD * 256) return;
        int q = idx2 / (DD * 256);
        rel = idx2 - q * (DD * 256);
        if (q < 3) { W = W1 + (size_t)q * DD * DD;       slot = 1 + q; }
        else       { W = W2 + (size_t)(q - 3) * DD * DD; slot = 1 + q; }
    }
    int kk = rel >> 8;
    int n  = rel & 255;
    float w = W[rel];
    __nv_bfloat16 hi = __float2bfloat16(w);
    __nv_bfloat16 lo = __float2bfloat16(w - __bfloat162float(hi));
    int nblk = n >> 7, nr = n & 127;
    int kchunk = kk >> 5, kc = kk & 31;
    int c8 = kc >> 3, w8 = kc & 7;
    size_t off = (size_t)slot * 65536 + ((size_t)nblk * 8 + kchunk) * 4096
               + (size_t)CIDX(nr, c8) * 8 + w8;
    g_Bhi[off] = hi;
    g_Blo[off] = lo;
}

// ======================= setup / CSR build ==================================
__global__ void zero_setup_kernel() {
    int i = blockIdx.x * blockDim.x + threadIdx.x;
    if (i < GG * DD * LL) g_pooled[i] = 0.f;
    if (i < GG)           g_cnt[i]    = 0.f;
    if (i < DD) { g_colsum[i] = 0.f; g_colsq[i] = 0.f; }
    if (i < NN) { g_deg[i] = 0; g_fill[i] = 0; }
}

__global__ void hist_count_kernel(const int* __restrict__ ei,
                                  const int* __restrict__ batch) {
    int e = blockIdx.x * blockDim.x + threadIdx.x;
    if (e < EE) atomicAdd(&g_deg[ei[EE + e]], 1);
    if (e < NN) atomicAdd(&g_cnt[batch[e]], 1.0f);
}

__global__ __launch_bounds__(1024)
void scan_kernel() {
    __shared__ int part[1024];
    const int t = threadIdx.x;
    const int per = (NN + 1023) / 1024;
    const int base = t * per;
    int s = 0;
    for (int i = 0; i < per; i++) {
        int idx = base + i;
        if (idx < NN) s += g_deg[idx];
    }
    part[t] = s;
    __syncthreads();
    for (int off = 1; off < 1024; off <<= 1) {
        int v = part[t];
        int u = (t >= off) ? part[t - off] : 0;
        __syncthreads();
        part[t] = v + u;
        __syncthreads();
    }
    int pre = (t > 0) ? part[t - 1] : 0;
    for (int i = 0; i < per; i++) {
        int idx = base + i;
        if (idx < NN) {
            int d = g_deg[idx];
            g_rowptr[idx] = pre;
            pre += d;
        }
    }
    if (t == 1023) g_rowptr[NN] = pre;
}

__global__ void fill_kernel(const int* __restrict__ ei) {
    int e = blockIdx.x * blockDim.x + threadIdx.x;
    if (e >= EE) return;
    int d = ei[EE + e];
    int pos = atomicAdd(&g_fill[d], 1);
    g_colidx[g_rowptr[d] + pos] = ei[e];
}

// ======================= gather -> pre-split swizzled A =====================
// self: fp32 from g_h; neighbors: fp16 from g_hb (one uint4 per lane/row)
__global__ __launch_bounds__(256)
void gather_kernel() {
    const int wid  = threadIdx.x >> 5;
    const int lane = threadIdx.x & 31;
    const int row  = blockIdx.x * 8 + wid;
    if (row >= NN) return;
    const int c0 = lane * 8;
    const float* hp = g_h + (size_t)row * DD + c0;
    float4 a0 = *(const float4*)hp;
    float4 a1 = *(const float4*)(hp + 4);
    int e  = g_rowptr[row];
    const int e1 = g_rowptr[row + 1];

#define NB_ADD(v)                                                        \
    do {                                                                 \
        float2 f0 = __half22float2(*reinterpret_cast<__half2*>(&(v).x)); \
        float2 f1 = __half22float2(*reinterpret_cast<__half2*>(&(v).y)); \
        float2 f2 = __half22float2(*reinterpret_cast<__half2*>(&(v).z)); \
        float2 f3 = __half22float2(*reinterpret_cast<__half2*>(&(v).w)); \
        a0.x += f0.x; a0.y += f0.y; a0.z += f1.x; a0.w += f1.y;          \
        a1.x += f2.x; a1.y += f2.y; a1.z += f3.x; a1.w += f3.y;          \
    } while (0)

    for (; e + 4 <= e1; e += 4) {
        int s0 = g_colidx[e];
        int s1 = g_colidx[e + 1];
        int s2 = g_colidx[e + 2];
        int s3 = g_colidx[e + 3];
        uint4 v0 = *(const uint4*)(g_hb + (size_t)s0 * DD + c0);
        uint4 v1 = *(const uint4*)(g_hb + (size_t)s1 * DD + c0);
        uint4 v2 = *(const uint4*)(g_hb + (size_t)s2 * DD + c0);
        uint4 v3 = *(const uint4*)(g_hb + (size_t)s3 * DD + c0);
        NB_ADD(v0);
        NB_ADD(v1);
        NB_ADD(v2);
        NB_ADD(v3);
    }
    for (; e < e1; e++) {
        int s = g_colidx[e];
        uint4 v = *(const uint4*)(g_hb + (size_t)s * DD + c0);
        NB_ADD(v);
    }
#undef NB_ADD

    // split + swizzled store (one 16B chunk per array)
    uint4 h4, l4;
    split2(a0.x, a0.y, h4.x, l4.x);
    split2(a0.z, a0.w, h4.y, l4.y);
    split2(a1.x, a1.y, h4.z, l4.z);
    split2(a1.z, a1.w, h4.w, l4.w);
    int mb = row >> 7, rr = row & 127;
    size_t ch = ((size_t)mb * 8 + (lane >> 2)) * 512 + CIDX(rr, lane & 3);
    ((uint4*)g_Ahi)[ch] = h4;
    ((uint4*)g_Alo)[ch] = l4;
}

// ======================= GEMM (conv path, encoder only) =====================
// writes fp32 C (g_h) and fp16 copy (g_hb)
__global__ __launch_bounds__(256, 2)
void mma_gemm_conv(const float* __restrict__ A, int K, int slot,
                   const float* __restrict__ bias,
                   float* __restrict__ C, int M) {
    extern __shared__ char dsm[];
    uint4* sAhi = (uint4*)dsm;
    uint4* sAlo = (uint4*)(dsm + 8192);

    const int tid  = threadIdx.x;
    const int wid  = tid >> 5, lane = tid & 31;
    const int bm   = blockIdx.y * 128;
    const int bn   = blockIdx.x * 128;
    const int wm   = (wid & 3) * 32;
    const int wn   = (wid >> 2) * 64;
    const int nChunks = K >> 5;

    const uint32_t sb = smem_to_u32(dsm);
    const uint32_t aHi = sb;
    const uint32_t aLo = sb + 8192;
    const uint32_t bHiA[2] = { sb + 16384, sb + 24576 };
    const uint32_t bLoA[2] = { sb + 32768, sb + 40960 };

    int arow[2];
    arow[0] = wm + (lane & 15);
    arow[1] = wm + 16 + (lane & 15);
    const int ac8 = lane >> 4;
    int brow[4];
#pragma unroll
    for (int nt2 = 0; nt2 < 4; nt2++)
        brow[nt2] = wn + nt2 * 16 + (lane >> 4) * 8 + (lane & 7);
    const int bc8 = (lane >> 3) & 1;

    const int lrow = tid >> 1;
    const int lcsel = tid & 1;
    const bool lok = (bm + lrow) < M;
    const float* ap = A + (size_t)(bm + lrow) * K + lcsel * 16;

    float acc[2][8][4];
#pragma unroll
    for (int mt = 0; mt < 2; mt++)
#pragma unroll
        for (int nt = 0; nt < 8; nt++)
#pragma unroll
            for (int i = 0; i < 4; i++) acc[mt][nt][i] = 0.f;

    const uint4* bsrc_hi = (const uint4*)(g_Bhi + (size_t)slot * 65536
                                          + (size_t)blockIdx.x * 8 * 4096);
    const uint4* bsrc_lo = (const uint4*)(g_Blo + (size_t)slot * 65536
                                          + (size_t)blockIdx.x * 8 * 4096);

    float4 pre0, pre1, pre2, pre3;
    {
        const float* apc = ap;
        pre0 = lok ? *(const float4*)(apc + 0)  : make_float4(0.f, 0.f, 0.f, 0.f);
        pre1 = lok ? *(const float4*)(apc + 4)  : make_float4(0.f, 0.f, 0.f, 0.f);
        pre2 = lok ? *(const float4*)(apc + 8)  : make_float4(0.f, 0.f, 0.f, 0.f);
        pre3 = lok ? *(const float4*)(apc + 12) : make_float4(0.f, 0.f, 0.f, 0.f);
        cpa16(bHiA[0] + tid * 16,        bsrc_hi + tid);
        cpa16(bHiA[0] + tid * 16 + 4096, bsrc_hi + tid + 256);
        cpa16(bLoA[0] + tid * 16,        bsrc_lo + tid);
        cpa16(bLoA[0] + tid * 16 + 4096, bsrc_lo + tid + 256);
        CPA_COMMIT();
    }

    for (int c = 0; c < nChunks; c++) {
        const int par = c & 1;
        CPA_WAIT0();
        __syncthreads();

        {
            uint4 h, l;
            split2(pre0.x, pre0.y, h.x, l.x);
            split2(pre0.z, pre0.w, h.y, l.y);
            split2(pre1.x, pre1.y, h.z, l.z);
            split2(pre1.z, pre1.w, h.w, l.w);
            int ci = CIDX(lrow, lcsel * 2);
            sAhi[ci] = h; sAlo[ci] = l;
            split2(pre2.x, pre2.y, h.x, l.x);
            split2(pre2.z, pre2.w, h.y, l.y);
            split2(pre3.x, pre3.y, h.z, l.z);
            split2(pre3.z, pre3.w, h.w, l.w);
            ci = CIDX(lrow, lcsel * 2 + 1);
            sAhi[ci] = h; sAlo[ci] = l;
        }
        if (c + 1 < nChunks) {
            const int np = (c + 1) & 1;
            const uint4* sh = bsrc_hi + (size_t)(c + 1) * 512;
            const uint4* sl = bsrc_lo + (size_t)(c + 1) * 512;
            cpa16(bHiA[np] + tid * 16,        sh + tid);
            cpa16(bHiA[np] + tid * 16 + 4096, sh + tid + 256);
            cpa16(bLoA[np] + tid * 16,        sl + tid);
            cpa16(bLoA[np] + tid * 16 + 4096, sl + tid + 256);
            CPA_COMMIT();
            const float* apc = ap + (c + 1) * 32;
            pre0 = lok ? *(const float4*)(apc + 0)  : make_float4(0.f, 0.f, 0.f, 0.f);
            pre1 = lok ? *(const float4*)(apc + 4)  : make_float4(0.f, 0.f, 0.f, 0.f);
            pre2 = lok ? *(const float4*)(apc + 8)  : make_float4(0.f, 0.f, 0.f, 0.f);
            pre3 = lok ? *(const float4*)(apc + 12) : make_float4(0.f, 0.f, 0.f, 0.f);
        } else {
            CPA_COMMIT();
        }
        __syncthreads();

#pragma unroll
        for (int kk2 = 0; kk2 < 2; kk2++) {
            uint32_t Ah[2][4], Al[2][4], Bh[4][4], Bl[4][4];
#pragma unroll
            for (int mt = 0; mt < 2; mt++) {
                int ci = CIDX(arow[mt], kk2 * 2 + ac8);
                ldsm_x4(Ah[mt], aHi + ci * 16);
                ldsm_x4(Al[mt], aLo + ci * 16);
            }
#pragma unroll
            for (int nt2 = 0; nt2 < 4; nt2++) {
                int ci = CIDX(brow[nt2], kk2 * 2 + bc8);
                ldsm_x4(Bh[nt2], bHiA[par] + ci * 16);
                ldsm_x4(Bl[nt2], bLoA[par] + ci * 16);
            }
#pragma unroll
            for (int mt = 0; mt < 2; mt++)
#pragma unroll
                for (int nt = 0; nt < 8; nt++) {
                    const uint32_t* ph = &Bh[nt >> 1][(nt & 1) * 2];
                    const uint32_t* pl = &Bl[nt >> 1][(nt & 1) * 2];
                    mma16816(acc[mt][nt], Ah[mt], ph);
                    mma16816(acc[mt][nt], Ah[mt], pl);
                    mma16816(acc[mt][nt], Al[mt], ph);
                }
        }
    }

    // epilogue: fp32 C + fp16 mirror
    const int col0 = bn + wn + (lane & 3) * 2;
    float2 bv[8];
#pragma unroll
    for (int nt = 0; nt < 8; nt++)
        bv[nt] = *(const float2*)&bias[col0 + nt * 8];

#pragma unroll
    for (int mt = 0; mt < 2; mt++) {
        int ra = bm + wm + mt * 16 + (lane >> 2);
#pragma unroll
        for (int half = 0; half < 2; half++) {
            int r = ra + half * 8;
            if (r < M) {
                size_t rowoff = (size_t)r * 256;
#pragma unroll
                for (int nt = 0; nt < 8; nt++) {
                    float2 o;
                    o.x = acc[mt][nt][half * 2 + 0] + bv[nt].x;
                    o.y = acc[mt][nt][half * 2 + 1] + bv[nt].y;
                    *(float2*)&C[rowoff + col0 + nt * 8] = o;
                    *(__half2*)&g_hb[rowoff + col0 + nt * 8] =
                        __floats2half2_rn(o.x, o.y);
                }
            }
        }
    }
}

// ======================= GEMM (pre-split A path) ============================
template <int RELU, int STATS, int TSPLIT>
__global__ __launch_bounds__(256, 2)
void mma_gemm_pre(const __nv_bfloat16* __restrict__ Ahi,
                  const __nv_bfloat16* __restrict__ Alo,
                  int slot, const float* __restrict__ bias,
                  float* __restrict__ C,
                  __nv_bfloat16* __restrict__ Thi,
                  __nv_bfloat16* __restrict__ Tlo, int M) {
    extern __shared__ char dsm[];
    __shared__ float scs[128], scq[128];

    const int tid  = threadIdx.x;
    const int wid  = tid >> 5, lane = tid & 31;
    const int bm   = blockIdx.y * 128;
    const int bn   = blockIdx.x * 128;
    const int wm   = (wid & 3) * 32;
    const int wn   = (wid >> 2) * 64;
    const int nChunks = 8;   // K = 256

    if (STATS) {
        if (tid < 128) { scs[tid] = 0.f; scq[tid] = 0.f; }
    }

    const uint32_t sb = smem_to_u32(dsm);
    const uint32_t aHiA[2] = { sb,         sb + 8192  };
    const uint32_t aLoA[2] = { sb + 16384, sb + 24576 };
    const uint32_t bHiA[2] = { sb + 32768, sb + 40960 };
    const uint32_t bLoA[2] = { sb + 49152, sb + 57344 };

    int arow[2];
    arow[0] = wm + (lane & 15);
    arow[1] = wm + 16 + (lane & 15);
    const int ac8 = lane >> 4;
    int brow[4];
#pragma unroll
    for (int nt2 = 0; nt2 < 4; nt2++)
        brow[nt2] = wn + nt2 * 16 + (lane >> 4) * 8 + (lane & 7);
    const int bc8 = (lane >> 3) & 1;

    float acc[2][8][4];
#pragma unroll
    for (int mt = 0; mt < 2; mt++)
#pragma unroll
        for (int nt = 0; nt < 8; nt++)
#pragma unroll
            for (int i = 0; i < 4; i++) acc[mt][nt][i] = 0.f;

    const uint4* asrc_hi = (const uint4*)Ahi + (size_t)blockIdx.y * 4096;
    const uint4* asrc_lo = (const uint4*)Alo + (size_t)blockIdx.y * 4096;
    const uint4* bsrc_hi = (const uint4*)(g_Bhi + (size_t)slot * 65536
                                          + (size_t)blockIdx.x * 8 * 4096);
    const uint4* bsrc_lo = (const uint4*)(g_Blo + (size_t)slot * 65536
                                          + (size_t)blockIdx.x * 8 * 4096);

#define LOAD_CHUNK(cc, buf)                                                    \
    do {                                                                       \
        const uint4* ah = asrc_hi + (size_t)(cc) * 512;                        \
        const uint4* al = asrc_lo + (size_t)(cc) * 512;                        \
        const uint4* bh = bsrc_hi + (size_t)(cc) * 512;                        \
        const uint4* bl = bsrc_lo + (size_t)(cc) * 512;                        \
        cpa16(aHiA[buf] + tid * 16,        ah + tid);                          \
        cpa16(aHiA[buf] + tid * 16 + 4096, ah + tid + 256);                    \
        cpa16(aLoA[buf] + tid * 16,        al + tid);                          \
        cpa16(aLoA[buf] + tid * 16 + 4096, al + tid + 256);                    \
        cpa16(bHiA[buf] + tid * 16,        bh + tid);                          \
        cpa16(bHiA[buf] + tid * 16 + 4096, bh + tid + 256);                    \
        cpa16(bLoA[buf] + tid * 16,        bl + tid);                          \
        cpa16(bLoA[buf] + tid * 16 + 4096, bl + tid + 256);                    \
        CPA_COMMIT();                                                          \
    } while (0)

    LOAD_CHUNK(0, 0);

    for (int c = 0; c < nChunks; c++) {
        const int par = c & 1;
        const int np  = par ^ 1;
        CPA_WAIT0();
        __syncthreads();

        if (c + 1 < nChunks) LOAD_CHUNK(c + 1, np);
        else CPA_COMMIT();

#pragma unroll
        for (int kk2 = 0; kk2 < 2; kk2++) {
            uint32_t Ah[2][4], Al[2][4], Bh[4][4], Bl[4][4];
#pragma unroll
            for (int mt = 0; mt < 2; mt++) {
                int ci = CIDX(arow[mt], kk2 * 2 + ac8);
                ldsm_x4(Ah[mt], aHiA[par] + ci * 16);
                ldsm_x4(Al[mt], aLoA[par] + ci * 16);
            }
#pragma unroll
            for (int nt2 = 0; nt2 < 4; nt2++) {
                int ci = CIDX(brow[nt2], kk2 * 2 + bc8);
                ldsm_x4(Bh[nt2], bHiA[par] + ci * 16);
                ldsm_x4(Bl[nt2], bLoA[par] + ci * 16);
            }
#pragma unroll
            for (int mt = 0; mt < 2; mt++)
#pragma unroll
                for (int nt = 0; nt < 8; nt++) {
                    const uint32_t* ph = &Bh[nt >> 1][(nt & 1) * 2];
                    const uint32_t* pl = &Bl[nt >> 1][(nt & 1) * 2];
                    mma16816(acc[mt][nt], Ah[mt], ph);
                    mma16816(acc[mt][nt], Ah[mt], pl);
                    mma16816(acc[mt][nt], Al[mt], ph);
                }
        }
    }
#undef LOAD_CHUNK

    // ---- epilogue ----
    const int col0 = bn + wn + (lane & 3) * 2;
    float2 bv[8];
#pragma unroll
    for (int nt = 0; nt < 8; nt++)
        bv[nt] = *(const float2*)&bias[col0 + nt * 8];

    float s_c[8][2], q_c[8][2];
    if (STATS) {
#pragma unroll
        for (int nt = 0; nt < 8; nt++) {
            s_c[nt][0] = s_c[nt][1] = 0.f;
            q_c[nt][0] = q_c[nt][1] = 0.f;
        }
    }

#pragma unroll
    for (int mt = 0; mt < 2; mt++) {
#pragma unroll
        for (int half = 0; half < 2; half++) {
            int rr = wm + mt * 16 + (lane >> 2) + half * 8;
            int r  = bm + rr;
            if (r < M) {
                size_t rowoff = (size_t)r * 256;
#pragma unroll
                for (int nt = 0; nt < 8; nt++) {
                    float2 o;
                    o.x = acc[mt][nt][half * 2 + 0] + bv[nt].x;
                    o.y = acc[mt][nt][half * 2 + 1] + bv[nt].y;
                    if (RELU) { o.x = fmaxf(o.x, 0.f); o.y = fmaxf(o.y, 0.f); }
                    if (STATS) {
                        s_c[nt][0] += o.x;          s_c[nt][1] += o.y;
                        q_c[nt][0] = fmaf(o.x, o.x, q_c[nt][0]);
                        q_c[nt][1] = fmaf(o.y, o.y, q_c[nt][1]);
                    }
                    if (TSPLIT) {
                        int colg = col0 + nt * 8;
                        int kc = colg >> 5;
                        int c8 = (colg >> 3) & 3;
                        size_t ch = ((size_t)blockIdx.y * 8 + kc) * 512
                                  + CIDX(rr, c8);
                        uint32_t hb, lb;
                        split2(o.x, o.y, hb, lb);
                        *(uint32_t*)((char*)Thi + ch * 16 + (lane & 3) * 4) = hb;
                        *(uint32_t*)((char*)Tlo + ch * 16 + (lane & 3) * 4) = lb;
                    } else {
                        *(float2*)&C[rowoff + col0 + nt * 8] = o;
                    }
                }
            }
        }
    }

    if (STATS) {
        const int cb = wn + (lane & 3) * 2;
#pragma unroll
        for (int nt = 0; nt < 8; nt++) {
            atomicAdd(&scs[cb + nt * 8],     s_c[nt][0]);
            atomicAdd(&scs[cb + nt * 8 + 1], s_c[nt][1]);
            atomicAdd(&scq[cb + nt * 8],     q_c[nt][0]);
            atomicAdd(&scq[cb + nt * 8 + 1], q_c[nt][1]);
        }
        __syncthreads();
        if (tid < 128) {
            atomicAdd(&g_colsum[bn + tid], scs[tid]);
            atomicAdd(&g_colsq[bn + tid],  scq[tid]);
        }
    }
}

// ======================= BN finalize (self-resetting) =======================
__global__ void finalize_stats_kernel(const float* __restrict__ gamma,
                                      const float* __restrict__ beta) {
    int c = threadIdx.x;
    float mean = g_colsum[c] * (1.0f / NN);
    float var  = g_colsq[c] * (1.0f / NN) - mean * mean;
    float sc   = gamma[c] * rsqrtf(var + BN_EPS);
    g_scale[c] = sc;
    g_shift[c] = beta[c] - mean * sc;
    g_colsum[c] = 0.f;
    g_colsq[c]  = 0.f;
}

// ======================= BN apply + ReLU + pool (+fp16 mirror) ==============
__global__ __launch_bounds__(256)
void bn_apply_kernel(const int* __restrict__ batch, int layer) {
    int row = blockIdx.x * 4 + (threadIdx.x >> 6);
    if (row >= NN) return;
    int c4 = (threadIdx.x & 63) * 4;
    float4 v  = *(const float4*)&g_z[(size_t)row * DD + c4];
    float4 sc = *(const float4*)&g_scale[c4];
    float4 sh = *(const float4*)&g_shift[c4];
    float4 o;
    o.x = fmaxf(fmaf(v.x, sc.x, sh.x), 0.f);
    o.y = fmaxf(fmaf(v.y, sc.y, sh.y), 0.f);
    o.z = fmaxf(fmaf(v.z, sc.z, sh.z), 0.f);
    o.w = fmaxf(fmaf(v.w, sc.w, sh.w), 0.f);
    size_t off = (size_t)row * DD + c4;
    *(float4*)&g_h[off] = o;
    *(__half2*)&g_hb[off]     = __floats2half2_rn(o.x, o.y);
    *(__half2*)&g_hb[off + 2] = __floats2half2_rn(o.z, o.w);
    int gidx = batch[row];
    red_add_v4(&g_pooled[(size_t)gidx * (DD * LL) + layer * DD + c4], o);
}

// ======================= MLP head ===========================================
__global__ __launch_bounds__(128)
void fc1_kernel(const float* __restrict__ W, const float* __restrict__ b) {
    int row = blockIdx.x;
    int j   = threadIdx.x;
    __shared__ float sp[DD * LL];
    for (int k = j; k < DD * LL; k += 128)
        sp[k] = g_pooled[(size_t)row * (DD * LL) + k];
    __syncthreads();
    float inv = 1.0f / fmaxf(g_cnt[row], 1.0f);
    float s = 0.f;
#pragma unroll 8
    for (int k = 0; k < DD * LL; k++)
        s = fmaf(sp[k], W[(size_t)k * 128 + j], s);
    g_hid[(size_t)row * 128 + j] = fmaxf(fmaf(s, inv, b[j]), 0.f);
}

__global__ __launch_bounds__(128)
void fc2_kernel(const float* __restrict__ W, const float* __restrict__ b,
                float* __restrict__ out) {
    int row = blockIdx.x;
    int t   = threadIdx.x;
    float v = g_hid[(size_t)row * 128 + t] * W[t];
#pragma unroll
    for (int off = 16; off; off >>= 1)
        v += __shfl_down_sync(0xFFFFFFFFu, v, off);
    __shared__ float ws[4];
    if ((t & 31) == 0) ws[t >> 5] = v;
    __syncthreads();
    if (t == 0) out[row] = ws[0] + ws[1] + ws[2] + ws[3] + b[0];
}

// ======================= launch ============================================
extern "C" void kernel_launch(void* const* d_in, const int* in_sizes, int n_in,
                              void* d_out, int out_size) {
    const float* x     = (const float*)d_in[0];
    const int*   ei    = (const int*)d_in[1];
    const int*   batch = (const int*)d_in[2];
    int base = n_in - 12;
    const float* W_enc = (const float*)d_in[base + 0];
    const float* b_enc = (const float*)d_in[base + 1];
    const float* W1    = (const float*)d_in[base + 2];
    const float* b1    = (const float*)d_in[base + 3];
    const float* W2    = (const float*)d_in[base + 4];
    const float* b2    = (const float*)d_in[base + 5];
    const float* gamma = (const float*)d_in[base + 6];
    const float* beta  = (const float*)d_in[base + 7];
    const float* Wf1   = (const float*)d_in[base + 8];
    const float* bf1   = (const float*)d_in[base + 9];
    const float* Wf2   = (const float*)d_in[base + 10];
    const float* bf2   = (const float*)d_in[base + 11];
    float* out = (float*)d_out;

    float *ph = nullptr, *pz = nullptr;
    __nv_bfloat16 *pAhi = nullptr, *pAlo = nullptr, *pThi = nullptr, *pTlo = nullptr;
    cudaGetSymbolAddress((void**)&ph, g_h);
    cudaGetSymbolAddress((void**)&pz, g_z);
    cudaGetSymbolAddress((void**)&pAhi, g_Ahi);
    cudaGetSymbolAddress((void**)&pAlo, g_Alo);
    cudaGetSymbolAddress((void**)&pThi, g_Thi);
    cudaGetSymbolAddress((void**)&pTlo, g_Tlo);

    const int SMB_CONV = 49152;
    const int SMB_PRE  = 65536;
    cudaFuncSetAttribute(mma_gemm_conv,
                         cudaFuncAttributeMaxDynamicSharedMemorySize, SMB_CONV);
    cudaFuncSetAttribute(mma_gemm_pre<1, 0, 1>,
                         cudaFuncAttributeMaxDynamicSharedMemorySize, SMB_PRE);
    cudaFuncSetAttribute(mma_gemm_pre<0, 1, 0>,
                         cudaFuncAttributeMaxDynamicSharedMemorySize, SMB_PRE);

    dim3 ge(2, (NN + 127) / 128);   // (nblk, 391)

    prep_all_weights_kernel<<<(FIN * 256 + 6 * DD * 256 + 255) / 256, 256>>>(
        W_enc, W1, W2);
    zero_setup_kernel<<<(GG * DD * LL + 255) / 256, 256>>>();
    hist_count_kernel<<<(EE + 255) / 256, 256>>>(ei, batch);
    mma_gemm_conv<<<ge, 256, SMB_CONV>>>(x, FIN, 0, b_enc, ph, NN);
    scan_kernel<<<1, 1024>>>();
    fill_kernel<<<(EE + 255) / 256, 256>>>(ei);

    for (int l = 0; l < LL; l++) {
        gather_kernel<<<(NN + 7) / 8, 256>>>();   // g_h/g_hb -> g_Ahi/g_Alo
        mma_gemm_pre<1, 0, 1><<<ge, 256, SMB_PRE>>>(
            pAhi, pAlo, 1 + l, b1 + l * DD, pz, pThi, pTlo, NN);   // t (split)
        mma_gemm_pre<0, 1, 0><<<ge, 256, SMB_PRE>>>(
            pThi, pTlo, 4 + l, b2 + l * DD, pz, pThi, pTlo, NN);   // z + stats
        finalize_stats_kernel<<<1, DD>>>(gamma + l * DD, beta + l * DD);
        bn_apply_kernel<<<NN / 4, 256>>>(batch, l);
    }

    fc1_kernel<<<GG, 128>>>(Wf1, bf1);
    fc2_kernel<<<GG, 128>>>(Wf2, bf2, out);
    (void)in_sizes; (void)out_size;
}

// round 14
// speedup vs baseline: 1.2705x; 1.0292x over previous
#include <cuda_runtime.h>
#include <cuda_bf16.h>
#include <cuda_fp16.h>
#include <cstdint>

#define NN   50000
#define EE   800000
#define FIN  128
#define DD   256
#define LL   3
#define GG   512
#define NPAD 50048          // 391 * 128
#define BN_EPS 1e-5f

// ======================= helpers ===========================================
__device__ __forceinline__ uint32_t smem_to_u32(const void* smem_ptr) {
    uint32_t addr;
    asm("{ .reg .u64 tmp; cvta.to.shared.u64 tmp, %1; cvt.u32.u64 %0, tmp; }"
        : "=r"(addr) : "l"(smem_ptr));
    return addr;
}
__device__ __forceinline__ void ldsm_x4(uint32_t* r, uint32_t addr) {
    asm volatile("ldmatrix.sync.aligned.m8n8.x4.shared.b16 {%0,%1,%2,%3}, [%4];"
        : "=r"(r[0]), "=r"(r[1]), "=r"(r[2]), "=r"(r[3]) : "r"(addr));
}
__device__ __forceinline__ void mma16816(float* d, const uint32_t* a,
                                         const uint32_t* b) {
    asm volatile(
        "mma.sync.aligned.m16n8k16.row.col.f32.bf16.bf16.f32 "
        "{%0,%1,%2,%3}, {%4,%5,%6,%7}, {%8,%9}, {%0,%1,%2,%3};"
        : "+f"(d[0]), "+f"(d[1]), "+f"(d[2]), "+f"(d[3])
        : "r"(a[0]), "r"(a[1]), "r"(a[2]), "r"(a[3]), "r"(b[0]), "r"(b[1]));
}
__device__ __forceinline__ void split2(float x, float y, uint32_t& h, uint32_t& l) {
    __nv_bfloat16 hx = __float2bfloat16(x), hy = __float2bfloat16(y);
    __nv_bfloat16 lx = __float2bfloat16(x - __bfloat162float(hx));
    __nv_bfloat16 ly = __float2bfloat16(y - __bfloat162float(hy));
    __nv_bfloat162 hh = __halves2bfloat162(hx, hy);
    __nv_bfloat162 ll = __halves2bfloat162(lx, ly);
    h = *reinterpret_cast<uint32_t*>(&hh);
    l = *reinterpret_cast<uint32_t*>(&ll);
}
__device__ __forceinline__ void red_add_v4(float* p, float4 v) {
    asm volatile("red.global.add.v4.f32 [%0], {%1,%2,%3,%4};"
                 :: "l"(p), "f"(v.x), "f"(v.y), "f"(v.z), "f"(v.w)
                 : "memory");
}
__device__ __forceinline__ void cpa16(uint32_t saddr, const void* g) {
    asm volatile("cp.async.cg.shared.global [%0], [%1], 16;"
                 :: "r"(saddr), "l"(g));
}
#define CPA_COMMIT() asm volatile("cp.async.commit_group;" ::: "memory")
#define CPA_WAIT0()  asm volatile("cp.async.wait_group 0;" ::: "memory")
#define CIDX(row, c8) ((row) * 4 + ((c8) ^ ((row) & 3)))

// ======================= scratch (device globals) ===========================
__device__ __align__(256) __half g_hb[(size_t)NN * DD];   // fp16 activations
__device__ __align__(256) float  g_z[(size_t)NN * DD];
__device__ __align__(256) float  g_colsum[DD];
__device__ __align__(256) float  g_colsq[DD];
__device__ __align__(256) float  g_scale[DD];
__device__ __align__(256) float  g_shift[DD];
__device__ __align__(256) float  g_pooled[(size_t)GG * DD * LL];
__device__ __align__(256) float  g_cnt[GG];
__device__ __align__(256) float  g_hid[(size_t)GG * (DD / 2)];
__device__ __align__(256) __nv_bfloat16 g_Bhi[7 * 65536];
__device__ __align__(256) __nv_bfloat16 g_Blo[7 * 65536];
// pre-split swizzled activations (A operands), tile layout [mb][kc][512x16B]
__device__ __align__(256) __nv_bfloat16 g_Ahi[(size_t)NPAD * DD];
__device__ __align__(256) __nv_bfloat16 g_Alo[(size_t)NPAD * DD];
__device__ __align__(256) __nv_bfloat16 g_Thi[(size_t)NPAD * DD];
__device__ __align__(256) __nv_bfloat16 g_Tlo[(size_t)NPAD * DD];
// CSR (dst-major)
__device__ __align__(256) int g_deg[NN];
__device__ __align__(256) int g_fill[NN];
__device__ __align__(256) int g_rowptr[NN + 1];
__device__ __align__(256) int g_colidx[EE];

// ======================= weight prep (all slots, one launch) ================
__global__ void prep_all_weights_kernel(const float* __restrict__ W_enc,
                                        const float* __restrict__ W1,
                                        const float* __restrict__ W2) {
    int idx = blockIdx.x * blockDim.x + threadIdx.x;
    const float* W;
    int slot, rel;
    if (idx < FIN * 256) {
        W = W_enc; slot = 0; rel = idx;
    } else {
        int idx2 = idx - FIN * 256;
        if (idx2 >= 6 * DD * 256) return;
        int q = idx2 / (DD * 256);
        rel = idx2 - q * (DD * 256);
        if (q < 3) { W = W1 + (size_t)q * DD * DD;       slot = 1 + q; }
        else       { W = W2 + (size_t)(q - 3) * DD * DD; slot = 1 + q; }
    }
    int kk = rel >> 8;
    int n  = rel & 255;
    float w = W[rel];
    __nv_bfloat16 hi = __float2bfloat16(w);
    __nv_bfloat16 lo = __float2bfloat16(w - __bfloat162float(hi));
    int nblk = n >> 7, nr = n & 127;
    int kchunk = kk >> 5, kc = kk & 31;
    int c8 = kc >> 3, w8 = kc & 7;
    size_t off = (size_t)slot * 65536 + ((size_t)nblk * 8 + kchunk) * 4096
               + (size_t)CIDX(nr, c8) * 8 + w8;
    g_Bhi[off] = hi;
    g_Blo[off] = lo;
}

// ======================= setup / CSR build ==================================
__global__ void zero_setup_kernel() {
    int i = blockIdx.x * blockDim.x + threadIdx.x;
    if (i < GG * DD * LL) g_pooled[i] = 0.f;
    if (i < GG)           g_cnt[i]    = 0.f;
    if (i < DD) { g_colsum[i] = 0.f; g_colsq[i] = 0.f; }
    if (i < NN) { g_deg[i] = 0; g_fill[i] = 0; }
}

__global__ void hist_count_kernel(const int* __restrict__ ei,
                                  const int* __restrict__ batch) {
    int e = blockIdx.x * blockDim.x + threadIdx.x;
    if (e < EE) atomicAdd(&g_deg[ei[EE + e]], 1);
    if (e < NN) atomicAdd(&g_cnt[batch[e]], 1.0f);
}

__global__ __launch_bounds__(1024)
void scan_kernel() {
    __shared__ int part[1024];
    const int t = threadIdx.x;
    const int per = (NN + 1023) / 1024;
    const int base = t * per;
    int s = 0;
    for (int i = 0; i < per; i++) {
        int idx = base + i;
        if (idx < NN) s += g_deg[idx];
    }
    part[t] = s;
    __syncthreads();
    for (int off = 1; off < 1024; off <<= 1) {
        int v = part[t];
        int u = (t >= off) ? part[t - off] : 0;
        __syncthreads();
        part[t] = v + u;
        __syncthreads();
    }
    int pre = (t > 0) ? part[t - 1] : 0;
    for (int i = 0; i < per; i++) {
        int idx = base + i;
        if (idx < NN) {
            int d = g_deg[idx];
            g_rowptr[idx] = pre;
            pre += d;
        }
    }
    if (t == 1023) g_rowptr[NN] = pre;
}

__global__ void fill_kernel(const int* __restrict__ ei) {
    int e = blockIdx.x * blockDim.x + threadIdx.x;
    if (e >= EE) return;
    int d = ei[EE + e];
    int pos = atomicAdd(&g_fill[d], 1);
    g_colidx[g_rowptr[d] + pos] = ei[e];
}

// ======================= gather -> pre-split swizzled A =====================
// self + neighbors all fp16 from g_hb; fp32 accumulate; split-store to A tiles
__global__ __launch_bounds__(256)
void gather_kernel() {
    const int wid  = threadIdx.x >> 5;
    const int lane = threadIdx.x & 31;
    const int row  = blockIdx.x * 8 + wid;
    if (row >= NN) return;
    const int c0 = lane * 8;
    float4 a0, a1;
    {
        uint4 v = *(const uint4*)(g_hb + (size_t)row * DD + c0);
        float2 f0 = __half22float2(*reinterpret_cast<__half2*>(&v.x));
        float2 f1 = __half22float2(*reinterpret_cast<__half2*>(&v.y));
        float2 f2 = __half22float2(*reinterpret_cast<__half2*>(&v.z));
        float2 f3 = __half22float2(*reinterpret_cast<__half2*>(&v.w));
        a0 = make_float4(f0.x, f0.y, f1.x, f1.y);
        a1 = make_float4(f2.x, f2.y, f3.x, f3.y);
    }
    int e  = g_rowptr[row];
    const int e1 = g_rowptr[row + 1];

#define NB_ADD(v)                                                        \
    do {                                                                 \
        float2 f0 = __half22float2(*reinterpret_cast<__half2*>(&(v).x)); \
        float2 f1 = __half22float2(*reinterpret_cast<__half2*>(&(v).y)); \
        float2 f2 = __half22float2(*reinterpret_cast<__half2*>(&(v).z)); \
        float2 f3 = __half22float2(*reinterpret_cast<__half2*>(&(v).w)); \
        a0.x += f0.x; a0.y += f0.y; a0.z += f1.x; a0.w += f1.y;          \
        a1.x += f2.x; a1.y += f2.y; a1.z += f3.x; a1.w += f3.y;          \
    } while (0)

    for (; e + 4 <= e1; e += 4) {
        int s0 = g_colidx[e];
        int s1 = g_colidx[e + 1];
        int s2 = g_colidx[e + 2];
        int s3 = g_colidx[e + 3];
        uint4 v0 = *(const uint4*)(g_hb + (size_t)s0 * DD + c0);
        uint4 v1 = *(const uint4*)(g_hb + (size_t)s1 * DD + c0);
        uint4 v2 = *(const uint4*)(g_hb + (size_t)s2 * DD + c0);
        uint4 v3 = *(const uint4*)(g_hb + (size_t)s3 * DD + c0);
        NB_ADD(v0);
        NB_ADD(v1);
        NB_ADD(v2);
        NB_ADD(v3);
    }
    for (; e < e1; e++) {
        int s = g_colidx[e];
        uint4 v = *(const uint4*)(g_hb + (size_t)s * DD + c0);
        NB_ADD(v);
    }
#undef NB_ADD

    uint4 h4, l4;
    split2(a0.x, a0.y, h4.x, l4.x);
    split2(a0.z, a0.w, h4.y, l4.y);
    split2(a1.x, a1.y, h4.z, l4.z);
    split2(a1.z, a1.w, h4.w, l4.w);
    int mb = row >> 7, rr = row & 127;
    size_t ch = ((size_t)mb * 8 + (lane >> 2)) * 512 + CIDX(rr, lane & 3);
    ((uint4*)g_Ahi)[ch] = h4;
    ((uint4*)g_Alo)[ch] = l4;
}

// ======================= GEMM (conv path, encoder only) =====================
// writes fp16 activations g_hb only
__global__ __launch_bounds__(256, 2)
void mma_gemm_conv(const float* __restrict__ A, int K, int slot,
                   const float* __restrict__ bias, int M) {
    extern __shared__ char dsm[];
    uint4* sAhi = (uint4*)dsm;
    uint4* sAlo = (uint4*)(dsm + 8192);

    const int tid  = threadIdx.x;
    const int wid  = tid >> 5, lane = tid & 31;
    const int bm   = blockIdx.y * 128;
    const int bn   = blockIdx.x * 128;
    const int wm   = (wid & 3) * 32;
    const int wn   = (wid >> 2) * 64;
    const int nChunks = K >> 5;

    const uint32_t sb = smem_to_u32(dsm);
    const uint32_t aHi = sb;
    const uint32_t aLo = sb + 8192;
    const uint32_t bHiA[2] = { sb + 16384, sb + 24576 };
    const uint32_t bLoA[2] = { sb + 32768, sb + 40960 };

    int arow[2];
    arow[0] = wm + (lane & 15);
    arow[1] = wm + 16 + (lane & 15);
    const int ac8 = lane >> 4;
    int brow[4];
#pragma unroll
    for (int nt2 = 0; nt2 < 4; nt2++)
        brow[nt2] = wn + nt2 * 16 + (lane >> 4) * 8 + (lane & 7);
    const int bc8 = (lane >> 3) & 1;

    const int lrow = tid >> 1;
    const int lcsel = tid & 1;
    const bool lok = (bm + lrow) < M;
    const float* ap = A + (size_t)(bm + lrow) * K + lcsel * 16;

    float acc[2][8][4];
#pragma unroll
    for (int mt = 0; mt < 2; mt++)
#pragma unroll
        for (int nt = 0; nt < 8; nt++)
#pragma unroll
            for (int i = 0; i < 4; i++) acc[mt][nt][i] = 0.f;

    const uint4* bsrc_hi = (const uint4*)(g_Bhi + (size_t)slot * 65536
                                          + (size_t)blockIdx.x * 8 * 4096);
    const uint4* bsrc_lo = (const uint4*)(g_Blo + (size_t)slot * 65536
                                          + (size_t)blockIdx.x * 8 * 4096);

    float4 pre0, pre1, pre2, pre3;
    {
        const float* apc = ap;
        pre0 = lok ? *(const float4*)(apc + 0)  : make_float4(0.f, 0.f, 0.f, 0.f);
        pre1 = lok ? *(const float4*)(apc + 4)  : make_float4(0.f, 0.f, 0.f, 0.f);
        pre2 = lok ? *(const float4*)(apc + 8)  : make_float4(0.f, 0.f, 0.f, 0.f);
        pre3 = lok ? *(const float4*)(apc + 12) : make_float4(0.f, 0.f, 0.f, 0.f);
        cpa16(bHiA[0] + tid * 16,        bsrc_hi + tid);
        cpa16(bHiA[0] + tid * 16 + 4096, bsrc_hi + tid + 256);
        cpa16(bLoA[0] + tid * 16,        bsrc_lo + tid);
        cpa16(bLoA[0] + tid * 16 + 4096, bsrc_lo + tid + 256);
        CPA_COMMIT();
    }

    for (int c = 0; c < nChunks; c++) {
        const int par = c & 1;
        CPA_WAIT0();
        __syncthreads();

        {
            uint4 h, l;
            split2(pre0.x, pre0.y, h.x, l.x);
            split2(pre0.z, pre0.w, h.y, l.y);
            split2(pre1.x, pre1.y, h.z, l.z);
            split2(pre1.z, pre1.w, h.w, l.w);
            int ci = CIDX(lrow, lcsel * 2);
            sAhi[ci] = h; sAlo[ci] = l;
            split2(pre2.x, pre2.y, h.x, l.x);
            split2(pre2.z, pre2.w, h.y, l.y);
            split2(pre3.x, pre3.y, h.z, l.z);
            split2(pre3.z, pre3.w, h.w, l.w);
            ci = CIDX(lrow, lcsel * 2 + 1);
            sAhi[ci] = h; sAlo[ci] = l;
        }
        if (c + 1 < nChunks) {
            const int np = (c + 1) & 1;
            const uint4* sh = bsrc_hi + (size_t)(c + 1) * 512;
            const uint4* sl = bsrc_lo + (size_t)(c + 1) * 512;
            cpa16(bHiA[np] + tid * 16,        sh + tid);
            cpa16(bHiA[np] + tid * 16 + 4096, sh + tid + 256);
            cpa16(bLoA[np] + tid * 16,        sl + tid);
            cpa16(bLoA[np] + tid * 16 + 4096, sl + tid + 256);
            CPA_COMMIT();
            const float* apc = ap + (c + 1) * 32;
            pre0 = lok ? *(const float4*)(apc + 0)  : make_float4(0.f, 0.f, 0.f, 0.f);
            pre1 = lok ? *(const float4*)(apc + 4)  : make_float4(0.f, 0.f, 0.f, 0.f);
            pre2 = lok ? *(const float4*)(apc + 8)  : make_float4(0.f, 0.f, 0.f, 0.f);
            pre3 = lok ? *(const float4*)(apc + 12) : make_float4(0.f, 0.f, 0.f, 0.f);
        } else {
            CPA_COMMIT();
        }
        __syncthreads();

#pragma unroll
        for (int kk2 = 0; kk2 < 2; kk2++) {
            uint32_t Ah[2][4], Al[2][4], Bh[4][4], Bl[4][4];
#pragma unroll
            for (int mt = 0; mt < 2; mt++) {
                int ci = CIDX(arow[mt], kk2 * 2 + ac8);
                ldsm_x4(Ah[mt], aHi + ci * 16);
                ldsm_x4(Al[mt], aLo + ci * 16);
            }
#pragma unroll
            for (int nt2 = 0; nt2 < 4; nt2++) {
                int ci = CIDX(brow[nt2], kk2 * 2 + bc8);
                ldsm_x4(Bh[nt2], bHiA[par] + ci * 16);
                ldsm_x4(Bl[nt2], bLoA[par] + ci * 16);
            }
#pragma unroll
            for (int mt = 0; mt < 2; mt++)
#pragma unroll
                for (int nt = 0; nt < 8; nt++) {
                    const uint32_t* ph = &Bh[nt >> 1][(nt & 1) * 2];
                    const uint32_t* pl = &Bl[nt >> 1][(nt & 1) * 2];
                    mma16816(acc[mt][nt], Ah[mt], ph);
                    mma16816(acc[mt][nt], Ah[mt], pl);
                    mma16816(acc[mt][nt], Al[mt], ph);
                }
        }
    }

    // epilogue: fp16 activations only
    const int col0 = bn + wn + (lane & 3) * 2;
    float2 bv[8];
#pragma unroll
    for (int nt = 0; nt < 8; nt++)
        bv[nt] = *(const float2*)&bias[col0 + nt * 8];

#pragma unroll
    for (int mt = 0; mt < 2; mt++) {
        int ra = bm + wm + mt * 16 + (lane >> 2);
#pragma unroll
        for (int half = 0; half < 2; half++) {
            int r = ra + half * 8;
            if (r < M) {
                size_t rowoff = (size_t)r * 256;
#pragma unroll
                for (int nt = 0; nt < 8; nt++) {
                    float ox = acc[mt][nt][half * 2 + 0] + bv[nt].x;
                    float oy = acc[mt][nt][half * 2 + 1] + bv[nt].y;
                    *(__half2*)&g_hb[rowoff + col0 + nt * 8] =
                        __floats2half2_rn(ox, oy);
                }
            }
        }
    }
}

// ======================= GEMM (pre-split A path) ============================
template <int RELU, int STATS, int TSPLIT>
__global__ __launch_bounds__(256, 2)
void mma_gemm_pre(const __nv_bfloat16* __restrict__ Ahi,
                  const __nv_bfloat16* __restrict__ Alo,
                  int slot, const float* __restrict__ bias,
                  float* __restrict__ C,
                  __nv_bfloat16* __restrict__ Thi,
                  __nv_bfloat16* __restrict__ Tlo, int M) {
    extern __shared__ char dsm[];
    __shared__ float scs[128], scq[128];

    const int tid  = threadIdx.x;
    const int wid  = tid >> 5, lane = tid & 31;
    const int bm   = blockIdx.y * 128;
    const int bn   = blockIdx.x * 128;
    const int wm   = (wid & 3) * 32;
    const int wn   = (wid >> 2) * 64;
    const int nChunks = 8;   // K = 256

    if (STATS) {
        if (tid < 128) { scs[tid] = 0.f; scq[tid] = 0.f; }
    }

    const uint32_t sb = smem_to_u32(dsm);
    const uint32_t aHiA[2] = { sb,         sb + 8192  };
    const uint32_t aLoA[2] = { sb + 16384, sb + 24576 };
    const uint32_t bHiA[2] = { sb + 32768, sb + 40960 };
    const uint32_t bLoA[2] = { sb + 49152, sb + 57344 };

    int arow[2];
    arow[0] = wm + (lane & 15);
    arow[1] = wm + 16 + (lane & 15);
    const int ac8 = lane >> 4;
    int brow[4];
#pragma unroll
    for (int nt2 = 0; nt2 < 4; nt2++)
        brow[nt2] = wn + nt2 * 16 + (lane >> 4) * 8 + (lane & 7);
    const int bc8 = (lane >> 3) & 1;

    float acc[2][8][4];
#pragma unroll
    for (int mt = 0; mt < 2; mt++)
#pragma unroll
        for (int nt = 0; nt < 8; nt++)
#pragma unroll
            for (int i = 0; i < 4; i++) acc[mt][nt][i] = 0.f;

    const uint4* asrc_hi = (const uint4*)Ahi + (size_t)blockIdx.y * 4096;
    const uint4* asrc_lo = (const uint4*)Alo + (size_t)blockIdx.y * 4096;
    const uint4* bsrc_hi = (const uint4*)(g_Bhi + (size_t)slot * 65536
                                          + (size_t)blockIdx.x * 8 * 4096);
    const uint4* bsrc_lo = (const uint4*)(g_Blo + (size_t)slot * 65536
                                          + (size_t)blockIdx.x * 8 * 4096);

#define LOAD_CHUNK(cc, buf)                                                    \
    do {                                                                       \
        const uint4* ah = asrc_hi + (size_t)(cc) * 512;                        \
        const uint4* al = asrc_lo + (size_t)(cc) * 512;                        \
        const uint4* bh = bsrc_hi + (size_t)(cc) * 512;                        \
        const uint4* bl = bsrc_lo + (size_t)(cc) * 512;                        \
        cpa16(aHiA[buf] + tid * 16,        ah + tid);                          \
        cpa16(aHiA[buf] + tid * 16 + 4096, ah + tid + 256);                    \
        cpa16(aLoA[buf] + tid * 16,        al + tid);                          \
        cpa16(aLoA[buf] + tid * 16 + 4096, al + tid + 256);                    \
        cpa16(bHiA[buf] + tid * 16,        bh + tid);                          \
        cpa16(bHiA[buf] + tid * 16 + 4096, bh + tid + 256);                    \
        cpa16(bLoA[buf] + tid * 16,        bl + tid);                          \
        cpa16(bLoA[buf] + tid * 16 + 4096, bl + tid + 256);                    \
        CPA_COMMIT();                                                          \
    } while (0)

    LOAD_CHUNK(0, 0);

    for (int c = 0; c < nChunks; c++) {
        const int par = c & 1;
        const int np  = par ^ 1;
        CPA_WAIT0();
        __syncthreads();

        if (c + 1 < nChunks) LOAD_CHUNK(c + 1, np);
        else CPA_COMMIT();

#pragma unroll
        for (int kk2 = 0; kk2 < 2; kk2++) {
            uint32_t Ah[2][4], Al[2][4], Bh[4][4], Bl[4][4];
#pragma unroll
            for (int mt = 0; mt < 2; mt++) {
                int ci = CIDX(arow[mt], kk2 * 2 + ac8);
                ldsm_x4(Ah[mt], aHiA[par] + ci * 16);
                ldsm_x4(Al[mt], aLoA[par] + ci * 16);
            }
#pragma unroll
            for (int nt2 = 0; nt2 < 4; nt2++) {
                int ci = CIDX(brow[nt2], kk2 * 2 + bc8);
                ldsm_x4(Bh[nt2], bHiA[par] + ci * 16);
                ldsm_x4(Bl[nt2], bLoA[par] + ci * 16);
            }
#pragma unroll
            for (int mt = 0; mt < 2; mt++)
#pragma unroll
                for (int nt = 0; nt < 8; nt++) {
                    const uint32_t* ph = &Bh[nt >> 1][(nt & 1) * 2];
                    const uint32_t* pl = &Bl[nt >> 1][(nt & 1) * 2];
                    mma16816(acc[mt][nt], Ah[mt], ph);
                    mma16816(acc[mt][nt], Ah[mt], pl);
                    mma16816(acc[mt][nt], Al[mt], ph);
                }
        }
    }
#undef LOAD_CHUNK

    // ---- epilogue ----
    const int col0 = bn + wn + (lane & 3) * 2;
    float2 bv[8];
#pragma unroll
    for (int nt = 0; nt < 8; nt++)
        bv[nt] = *(const float2*)&bias[col0 + nt * 8];

    float s_c[8][2], q_c[8][2];
    if (STATS) {
#pragma unroll
        for (int nt = 0; nt < 8; nt++) {
            s_c[nt][0] = s_c[nt][1] = 0.f;
            q_c[nt][0] = q_c[nt][1] = 0.f;
        }
    }

#pragma unroll
    for (int mt = 0; mt < 2; mt++) {
#pragma unroll
        for (int half = 0; half < 2; half++) {
            int rr = wm + mt * 16 + (lane >> 2) + half * 8;
            int r  = bm + rr;
            if (r < M) {
                size_t rowoff = (size_t)r * 256;
#pragma unroll
                for (int nt = 0; nt < 8; nt++) {
                    float2 o;
                    o.x = acc[mt][nt][half * 2 + 0] + bv[nt].x;
                    o.y = acc[mt][nt][half * 2 + 1] + bv[nt].y;
                    if (RELU) { o.x = fmaxf(o.x, 0.f); o.y = fmaxf(o.y, 0.f); }
                    if (STATS) {
                        s_c[nt][0] += o.x;          s_c[nt][1] += o.y;
                        q_c[nt][0] = fmaf(o.x, o.x, q_c[nt][0]);
                        q_c[nt][1] = fmaf(o.y, o.y, q_c[nt][1]);
                    }
                    if (TSPLIT) {
                        int colg = col0 + nt * 8;
                        int kc = colg >> 5;
                        int c8 = (colg >> 3) & 3;
                        size_t ch = ((size_t)blockIdx.y * 8 + kc) * 512
                                  + CIDX(rr, c8);
                        uint32_t hb, lb;
                        split2(o.x, o.y, hb, lb);
                        *(uint32_t*)((char*)Thi + ch * 16 + (lane & 3) * 4) = hb;
                        *(uint32_t*)((char*)Tlo + ch * 16 + (lane & 3) * 4) = lb;
                    } else {
                        *(float2*)&C[rowoff + col0 + nt * 8] = o;
                    }
                }
            }
        }
    }

    if (STATS) {
        const int cb = wn + (lane & 3) * 2;
#pragma unroll
        for (int nt = 0; nt < 8; nt++) {
            atomicAdd(&scs[cb + nt * 8],     s_c[nt][0]);
            atomicAdd(&scs[cb + nt * 8 + 1], s_c[nt][1]);
            atomicAdd(&scq[cb + nt * 8],     q_c[nt][0]);
            atomicAdd(&scq[cb + nt * 8 + 1], q_c[nt][1]);
        }
        __syncthreads();
        if (tid < 128) {
            atomicAdd(&g_colsum[bn + tid], scs[tid]);
            atomicAdd(&g_colsq[bn + tid],  scq[tid]);
        }
    }
}

// ======================= BN finalize (self-resetting) =======================
__global__ void finalize_stats_kernel(const float* __restrict__ gamma,
                                      const float* __restrict__ beta) {
    int c = threadIdx.x;
    float mean = g_colsum[c] * (1.0f / NN);
    float var  = g_colsq[c] * (1.0f / NN) - mean * mean;
    float sc   = gamma[c] * rsqrtf(var + BN_EPS);
    g_scale[c] = sc;
    g_shift[c] = beta[c] - mean * sc;
    g_colsum[c] = 0.f;
    g_colsq[c]  = 0.f;
}

// ======================= BN apply + ReLU + pool (fp16 out) ==================
__global__ __launch_bounds__(256)
void bn_apply_kernel(const int* __restrict__ batch, int layer) {
    int row = blockIdx.x * 4 + (threadIdx.x >> 6);
    if (row >= NN) return;
    int c4 = (threadIdx.x & 63) * 4;
    float4 v  = *(const float4*)&g_z[(size_t)row * DD + c4];
    float4 sc = *(const float4*)&g_scale[c4];
    float4 sh = *(const float4*)&g_shift[c4];
    float4 o;
    o.x = fmaxf(fmaf(v.x, sc.x, sh.x), 0.f);
    o.y = fmaxf(fmaf(v.y, sc.y, sh.y), 0.f);
    o.z = fmaxf(fmaf(v.z, sc.z, sh.z), 0.f);
    o.w = fmaxf(fmaf(v.w, sc.w, sh.w), 0.f);
    size_t off = (size_t)row * DD + c4;
    *(__half2*)&g_hb[off]     = __floats2half2_rn(o.x, o.y);
    *(__half2*)&g_hb[off + 2] = __floats2half2_rn(o.z, o.w);
    int gidx = batch[row];
    red_add_v4(&g_pooled[(size_t)gidx * (DD * LL) + layer * DD + c4], o);
}

// ======================= MLP head ===========================================
__global__ __launch_bounds__(128)
void fc1_kernel(const float* __restrict__ W, const float* __restrict__ b) {
    int row = blockIdx.x;
    int j   = threadIdx.x;
    __shared__ float sp[DD * LL];
    for (int k = j; k < DD * LL; k += 128)
        sp[k] = g_pooled[(size_t)row * (DD * LL) + k];
    __syncthreads();
    float inv = 1.0f / fmaxf(g_cnt[row], 1.0f);
    float s = 0.f;
#pragma unroll 8
    for (int k = 0; k < DD * LL; k++)
        s = fmaf(sp[k], W[(size_t)k * 128 + j], s);
    g_hid[(size_t)row * 128 + j] = fmaxf(fmaf(s, inv, b[j]), 0.f);
}

__global__ __launch_bounds__(128)
void fc2_kernel(const float* __restrict__ W, const float* __restrict__ b,
                float* __restrict__ out) {
    int row = blockIdx.x;
    int t   = threadIdx.x;
    float v = g_hid[(size_t)row * 128 + t] * W[t];
#pragma unroll
    for (int off = 16; off; off >>= 1)
        v += __shfl_down_sync(0xFFFFFFFFu, v, off);
    __shared__ float ws[4];
    if ((t & 31) == 0) ws[t >> 5] = v;
    __syncthreads();
    if (t == 0) out[row] = ws[0] + ws[1] + ws[2] + ws[3] + b[0];
}

// ======================= launch ============================================
extern "C" void kernel_launch(void* const* d_in, const int* in_sizes, int n_in,
                              void* d_out, int out_size) {
    const float* x     = (const float*)d_in[0];
    const int*   ei    = (const int*)d_in[1];
    const int*   batch = (const int*)d_in[2];
    int base = n_in - 12;
    const float* W_enc = (const float*)d_in[base + 0];
    const float* b_enc = (const float*)d_in[base + 1];
    const float* W1    = (const float*)d_in[base + 2];
    const float* b1    = (const float*)d_in[base + 3];
    const float* W2    = (const float*)d_in[base + 4];
    const float* b2    = (const float*)d_in[base + 5];
    const float* gamma = (const float*)d_in[base + 6];
    const float* beta  = (const float*)d_in[base + 7];
    const float* Wf1   = (const float*)d_in[base + 8];
    const float* bf1   = (const float*)d_in[base + 9];
    const float* Wf2   = (const float*)d_in[base + 10];
    const float* bf2   = (const float*)d_in[base + 11];
    float* out = (float*)d_out;

    float* pz = nullptr;
    __nv_bfloat16 *pAhi = nullptr, *pAlo = nullptr, *pThi = nullptr, *pTlo = nullptr;
    cudaGetSymbolAddress((void**)&pz, g_z);
    cudaGetSymbolAddress((void**)&pAhi, g_Ahi);
    cudaGetSymbolAddress((void**)&pAlo, g_Alo);
    cudaGetSymbolAddress((void**)&pThi, g_Thi);
    cudaGetSymbolAddress((void**)&pTlo, g_Tlo);

    const int SMB_CONV = 49152;
    const int SMB_PRE  = 65536;
    cudaFuncSetAttribute(mma_gemm_conv,
                         cudaFuncAttributeMaxDynamicSharedMemorySize, SMB_CONV);
    cudaFuncSetAttribute(mma_gemm_pre<1, 0, 1>,
                         cudaFuncAttributeMaxDynamicSharedMemorySize, SMB_PRE);
    cudaFuncSetAttribute(mma_gemm_pre<0, 1, 0>,
                         cudaFuncAttributeMaxDynamicSharedMemorySize, SMB_PRE);

    dim3 ge(2, (NN + 127) / 128);   // (nblk, 391)

    prep_all_weights_kernel<<<(FIN * 256 + 6 * DD * 256 + 255) / 256, 256>>>(
        W_enc, W1, W2);
    zero_setup_kernel<<<(GG * DD * LL + 255) / 256, 256>>>();
    hist_count_kernel<<<(EE + 255) / 256, 256>>>(ei, batch);
    mma_gemm_conv<<<ge, 256, SMB_CONV>>>(x, FIN, 0, b_enc, NN);
    scan_kernel<<<1, 1024>>>();
    fill_kernel<<<(EE + 255) / 256, 256>>>(ei);

    for (int l = 0; l < LL; l++) {
        gather_kernel<<<(NN + 7) / 8, 256>>>();   // g_hb -> g_Ahi/g_Alo
        mma_gemm_pre<1, 0, 1><<<ge, 256, SMB_PRE>>>(
            pAhi, pAlo, 1 + l, b1 + l * DD, pz, pThi, pTlo, NN);   // t (split)
        mma_gemm_pre<0, 1, 0><<<ge, 256, SMB_PRE>>>(
            pThi, pTlo, 4 + l, b2 + l * DD, pz, pThi, pTlo, NN);   // z + stats
        finalize_stats_kernel<<<1, DD>>>(gamma + l * DD, beta + l * DD);
        bn_apply_kernel<<<NN / 4, 256>>>(batch, l);
    }

    fc1_kernel<<<GG, 128>>>(Wf1, bf1);
    fc2_kernel<<<GG, 128>>>(Wf2, bf2, out);
    (void)in_sizes; (void)out_size;
}

// round 17
// speedup vs baseline: 1.2844x; 1.0109x over previous
#include <cuda_runtime.h>
#include <cuda_bf16.h>
#include <cuda_fp16.h>
#include <cstdint>

#define NN   50000
#define EE   800000
#define FIN  128
#define DD   256
#define LL   3
#define GG   512
#define NPAD 50048          // 391 * 128
#define BN_EPS 1e-5f

// ======================= helpers ===========================================
__device__ __forceinline__ uint32_t smem_to_u32(const void* smem_ptr) {
    uint32_t addr;
    asm("{ .reg .u64 tmp; cvta.to.shared.u64 tmp, %1; cvt.u32.u64 %0, tmp; }"
        : "=r"(addr) : "l"(smem_ptr));
    return addr;
}
__device__ __forceinline__ void ldsm_x4(uint32_t* r, uint32_t addr) {
    asm volatile("ldmatrix.sync.aligned.m8n8.x4.shared.b16 {%0,%1,%2,%3}, [%4];"
        : "=r"(r[0]), "=r"(r[1]), "=r"(r[2]), "=r"(r[3]) : "r"(addr));
}
__device__ __forceinline__ void mma16816(float* d, const uint32_t* a,
                                         const uint32_t* b) {
    asm volatile(
        "mma.sync.aligned.m16n8k16.row.col.f32.bf16.bf16.f32 "
        "{%0,%1,%2,%3}, {%4,%5,%6,%7}, {%8,%9}, {%0,%1,%2,%3};"
        : "+f"(d[0]), "+f"(d[1]), "+f"(d[2]), "+f"(d[3])
        : "r"(a[0]), "r"(a[1]), "r"(a[2]), "r"(a[3]), "r"(b[0]), "r"(b[1]));
}
__device__ __forceinline__ void split2(float x, float y, uint32_t& h, uint32_t& l) {
    __nv_bfloat16 hx = __float2bfloat16(x), hy = __float2bfloat16(y);
    __nv_bfloat16 lx = __float2bfloat16(x - __bfloat162float(hx));
    __nv_bfloat16 ly = __float2bfloat16(y - __bfloat162float(hy));
    __nv_bfloat162 hh = __halves2bfloat162(hx, hy);
    __nv_bfloat162 ll = __halves2bfloat162(lx, ly);
    h = *reinterpret_cast<uint32_t*>(&hh);
    l = *reinterpret_cast<uint32_t*>(&ll);
}
__device__ __forceinline__ void red_add_v4(float* p, float4 v) {
    asm volatile("red.global.add.v4.f32 [%0], {%1,%2,%3,%4};"
                 :: "l"(p), "f"(v.x), "f"(v.y), "f"(v.z), "f"(v.w)
                 : "memory");
}
__device__ __forceinline__ void cpa16(uint32_t saddr, const void* g) {
    asm volatile("cp.async.cg.shared.global [%0], [%1], 16;"
                 :: "r"(saddr), "l"(g));
}
#define CPA_COMMIT() asm volatile("cp.async.commit_group;" ::: "memory")
#define CPA_WAIT0()  asm volatile("cp.async.wait_group 0;" ::: "memory")
#define CPA_WAIT1()  asm volatile("cp.async.wait_group 1;" ::: "memory")
#define CIDX(row, c8) ((row) * 4 + ((c8) ^ ((row) & 3)))

// ======================= scratch (device globals) ===========================
__device__ __align__(256) __half g_hb[(size_t)NN * DD];   // fp16 activations
__device__ __align__(256) float  g_z[(size_t)NN * DD];
__device__ __align__(256) float  g_colsum[DD];
__device__ __align__(256) float  g_colsq[DD];
__device__ __align__(256) float  g_scale[DD];
__device__ __align__(256) float  g_shift[DD];
__device__ __align__(256) float  g_pooled[(size_t)GG * DD * LL];
__device__ __align__(256) float  g_cnt[GG];
__device__ __align__(256) float  g_hid[(size_t)GG * (DD / 2)];
__device__ __align__(256) __nv_bfloat16 g_Bhi[7 * 65536];
__device__ __align__(256) __nv_bfloat16 g_Blo[7 * 65536];
// pre-split swizzled activations (A operands), tile layout [mb][kc][512x16B]
__device__ __align__(256) __nv_bfloat16 g_Ahi[(size_t)NPAD * DD];
__device__ __align__(256) __nv_bfloat16 g_Alo[(size_t)NPAD * DD];
__device__ __align__(256) __nv_bfloat16 g_Thi[(size_t)NPAD * DD];
__device__ __align__(256) __nv_bfloat16 g_Tlo[(size_t)NPAD * DD];
// CSR (dst-major)
__device__ __align__(256) int g_deg[NN];
__device__ __align__(256) int g_fill[NN];
__device__ __align__(256) int g_rowptr[NN + 1];
__device__ __align__(256) int g_colidx[EE];

// ======================= weight prep (all slots, one launch) ================
__global__ void prep_all_weights_kernel(const float* __restrict__ W_enc,
                                        const float* __restrict__ W1,
                                        const float* __restrict__ W2) {
    int idx = blockIdx.x * blockDim.x + threadIdx.x;
    const float* W;
    int slot, rel;
    if (idx < FIN * 256) {
        W = W_enc; slot = 0; rel = idx;
    } else {
        int idx2 = idx - FIN * 256;
        if (idx2 >= 6 * DD * 256) return;
        int q = idx2 / (DD * 256);
        rel = idx2 - q * (DD * 256);
        if (q < 3) { W = W1 + (size_t)q * DD * DD;       slot = 1 + q; }
        else       { W = W2 + (size_t)(q - 3) * DD * DD; slot = 1 + q; }
    }
    int kk = rel >> 8;
    int n  = rel & 255;
    float w = W[rel];
    __nv_bfloat16 hi = __float2bfloat16(w);
    __nv_bfloat16 lo = __float2bfloat16(w - __bfloat162float(hi));
    int nblk = n >> 7, nr = n & 127;
    int kchunk = kk >> 5, kc = kk & 31;
    int c8 = kc >> 3, w8 = kc & 7;
    size_t off = (size_t)slot * 65536 + ((size_t)nblk * 8 + kchunk) * 4096
               + (size_t)CIDX(nr, c8) * 8 + w8;
    g_Bhi[off] = hi;
    g_Blo[off] = lo;
}

// ======================= setup / CSR build ==================================
__global__ void zero_setup_kernel() {
    int i = blockIdx.x * blockDim.x + threadIdx.x;
    if (i < GG * DD * LL) g_pooled[i] = 0.f;
    if (i < GG)           g_cnt[i]    = 0.f;
    if (i < DD) { g_colsum[i] = 0.f; g_colsq[i] = 0.f; }
    if (i < NN) { g_deg[i] = 0; g_fill[i] = 0; }
}

__global__ void hist_count_kernel(const int* __restrict__ ei,
                                  const int* __restrict__ batch) {
    int e = blockIdx.x * blockDim.x + threadIdx.x;
    if (e < EE) atomicAdd(&g_deg[ei[EE + e]], 1);
    if (e < NN) atomicAdd(&g_cnt[batch[e]], 1.0f);
}

__global__ __launch_bounds__(1024)
void scan_kernel() {
    __shared__ int part[1024];
    const int t = threadIdx.x;
    const int per = (NN + 1023) / 1024;
    const int base = t * per;
    int s = 0;
    for (int i = 0; i < per; i++) {
        int idx = base + i;
        if (idx < NN) s += g_deg[idx];
    }
    part[t] = s;
    __syncthreads();
    for (int off = 1; off < 1024; off <<= 1) {
        int v = part[t];
        int u = (t >= off) ? part[t - off] : 0;
        __syncthreads();
        part[t] = v + u;
        __syncthreads();
    }
    int pre = (t > 0) ? part[t - 1] : 0;
    for (int i = 0; i < per; i++) {
        int idx = base + i;
        if (idx < NN) {
            int d = g_deg[idx];
            g_rowptr[idx] = pre;
            pre += d;
        }
    }
    if (t == 1023) g_rowptr[NN] = pre;
}

__global__ void fill_kernel(const int* __restrict__ ei) {
    int e = blockIdx.x * blockDim.x + threadIdx.x;
    if (e >= EE) return;
    int d = ei[EE + e];
    int pos = atomicAdd(&g_fill[d], 1);
    g_colidx[g_rowptr[d] + pos] = ei[e];
}

// ======================= gather -> pre-split swizzled A =====================
__global__ __launch_bounds__(256)
void gather_kernel() {
    const int wid  = threadIdx.x >> 5;
    const int lane = threadIdx.x & 31;
    const int row  = blockIdx.x * 8 + wid;
    if (row >= NN) return;
    const int c0 = lane * 8;
    float4 a0, a1;
    {
        uint4 v = *(const uint4*)(g_hb + (size_t)row * DD + c0);
        float2 f0 = __half22float2(*reinterpret_cast<__half2*>(&v.x));
        float2 f1 = __half22float2(*reinterpret_cast<__half2*>(&v.y));
        float2 f2 = __half22float2(*reinterpret_cast<__half2*>(&v.z));
        float2 f3 = __half22float2(*reinterpret_cast<__half2*>(&v.w));
        a0 = make_float4(f0.x, f0.y, f1.x, f1.y);
        a1 = make_float4(f2.x, f2.y, f3.x, f3.y);
    }
    int e  = g_rowptr[row];
    const int e1 = g_rowptr[row + 1];

#define NB_ADD(v)                                                        \
    do {                                                                 \
        float2 f0 = __half22float2(*reinterpret_cast<__half2*>(&(v).x)); \
        float2 f1 = __half22float2(*reinterpret_cast<__half2*>(&(v).y)); \
        float2 f2 = __half22float2(*reinterpret_cast<__half2*>(&(v).z)); \
        float2 f3 = __half22float2(*reinterpret_cast<__half2*>(&(v).w)); \
        a0.x += f0.x; a0.y += f0.y; a0.z += f1.x; a0.w += f1.y;          \
        a1.x += f2.x; a1.y += f2.y; a1.z += f3.x; a1.w += f3.y;          \
    } while (0)

    for (; e + 4 <= e1; e += 4) {
        int s0 = g_colidx[e];
        int s1 = g_colidx[e + 1];
        int s2 = g_colidx[e + 2];
        int s3 = g_colidx[e + 3];
        uint4 v0 = *(const uint4*)(g_hb + (size_t)s0 * DD + c0);
        uint4 v1 = *(const uint4*)(g_hb + (size_t)s1 * DD + c0);
        uint4 v2 = *(const uint4*)(g_hb + (size_t)s2 * DD + c0);
        uint4 v3 = *(const uint4*)(g_hb + (size_t)s3 * DD + c0);
        NB_ADD(v0);
        NB_ADD(v1);
        NB_ADD(v2);
        NB_ADD(v3);
    }
    for (; e < e1; e++) {
        int s = g_colidx[e];
        uint4 v = *(const uint4*)(g_hb + (size_t)s * DD + c0);
        NB_ADD(v);
    }
#undef NB_ADD

    uint4 h4, l4;
    split2(a0.x, a0.y, h4.x, l4.x);
    split2(a0.z, a0.w, h4.y, l4.y);
    split2(a1.x, a1.y, h4.z, l4.z);
    split2(a1.z, a1.w, h4.w, l4.w);
    int mb = row >> 7, rr = row & 127;
    size_t ch = ((size_t)mb * 8 + (lane >> 2)) * 512 + CIDX(rr, lane & 3);
    ((uint4*)g_Ahi)[ch] = h4;
    ((uint4*)g_Alo)[ch] = l4;
}

// ======================= GEMM (conv path, encoder only) =====================
__global__ __launch_bounds__(256, 2)
void mma_gemm_conv(const float* __restrict__ A, int K, int slot,
                   const float* __restrict__ bias, int M) {
    extern __shared__ char dsm[];
    uint4* sAhi = (uint4*)dsm;
    uint4* sAlo = (uint4*)(dsm + 8192);

    const int tid  = threadIdx.x;
    const int wid  = tid >> 5, lane = tid & 31;
    const int bm   = blockIdx.y * 128;
    const int bn   = blockIdx.x * 128;
    const int wm   = (wid & 3) * 32;
    const int wn   = (wid >> 2) * 64;
    const int nChunks = K >> 5;

    const uint32_t sb = smem_to_u32(dsm);
    const uint32_t aHi = sb;
    const uint32_t aLo = sb + 8192;
    const uint32_t bHiA[2] = { sb + 16384, sb + 24576 };
    const uint32_t bLoA[2] = { sb + 32768, sb + 40960 };

    int arow[2];
    arow[0] = wm + (lane & 15);
    arow[1] = wm + 16 + (lane & 15);
    const int ac8 = lane >> 4;
    int brow[4];
#pragma unroll
    for (int nt2 = 0; nt2 < 4; nt2++)
        brow[nt2] = wn + nt2 * 16 + (lane >> 4) * 8 + (lane & 7);
    const int bc8 = (lane >> 3) & 1;

    const int lrow = tid >> 1;
    const int lcsel = tid & 1;
    const bool lok = (bm + lrow) < M;
    const float* ap = A + (size_t)(bm + lrow) * K + lcsel * 16;

    float acc[2][8][4];
#pragma unroll
    for (int mt = 0; mt < 2; mt++)
#pragma unroll
        for (int nt = 0; nt < 8; nt++)
#pragma unroll
            for (int i = 0; i < 4; i++) acc[mt][nt][i] = 0.f;

    const uint4* bsrc_hi = (const uint4*)(g_Bhi + (size_t)slot * 65536
                                          + (size_t)blockIdx.x * 8 * 4096);
    const uint4* bsrc_lo = (const uint4*)(g_Blo + (size_t)slot * 65536
                                          + (size_t)blockIdx.x * 8 * 4096);

    float4 pre0, pre1, pre2, pre3;
    {
        const float* apc = ap;
        pre0 = lok ? *(const float4*)(apc + 0)  : make_float4(0.f, 0.f, 0.f, 0.f);
        pre1 = lok ? *(const float4*)(apc + 4)  : make_float4(0.f, 0.f, 0.f, 0.f);
        pre2 = lok ? *(const float4*)(apc + 8)  : make_float4(0.f, 0.f, 0.f, 0.f);
        pre3 = lok ? *(const float4*)(apc + 12) : make_float4(0.f, 0.f, 0.f, 0.f);
        cpa16(bHiA[0] + tid * 16,        bsrc_hi + tid);
        cpa16(bHiA[0] + tid * 16 + 4096, bsrc_hi + tid + 256);
        cpa16(bLoA[0] + tid * 16,        bsrc_lo + tid);
        cpa16(bLoA[0] + tid * 16 + 4096, bsrc_lo + tid + 256);
        CPA_COMMIT();
    }

    for (int c = 0; c < nChunks; c++) {
        const int par = c & 1;
        CPA_WAIT0();
        __syncthreads();

        {
            uint4 h, l;
            split2(pre0.x, pre0.y, h.x, l.x);
            split2(pre0.z, pre0.w, h.y, l.y);
            split2(pre1.x, pre1.y, h.z, l.z);
            split2(pre1.z, pre1.w, h.w, l.w);
            int ci = CIDX(lrow, lcsel * 2);
            sAhi[ci] = h; sAlo[ci] = l;
            split2(pre2.x, pre2.y, h.x, l.x);
            split2(pre2.z, pre2.w, h.y, l.y);
            split2(pre3.x, pre3.y, h.z, l.z);
            split2(pre3.z, pre3.w, h.w, l.w);
            ci = CIDX(lrow, lcsel * 2 + 1);
            sAhi[ci] = h; sAlo[ci] = l;
        }
        if (c + 1 < nChunks) {
            const int np = (c + 1) & 1;
            const uint4* sh = bsrc_hi + (size_t)(c + 1) * 512;
            const uint4* sl = bsrc_lo + (size_t)(c + 1) * 512;
            cpa16(bHiA[np] + tid * 16,        sh + tid);
            cpa16(bHiA[np] + tid * 16 + 4096, sh + tid + 256);
            cpa16(bLoA[np] + tid * 16,        sl + tid);
            cpa16(bLoA[np] + tid * 16 + 4096, sl + tid + 256);
            CPA_COMMIT();
            const float* apc = ap + (c + 1) * 32;
            pre0 = lok ? *(const float4*)(apc + 0)  : make_float4(0.f, 0.f, 0.f, 0.f);
            pre1 = lok ? *(const float4*)(apc + 4)  : make_float4(0.f, 0.f, 0.f, 0.f);
            pre2 = lok ? *(const float4*)(apc + 8)  : make_float4(0.f, 0.f, 0.f, 0.f);
            pre3 = lok ? *(const float4*)(apc + 12) : make_float4(0.f, 0.f, 0.f, 0.f);
        } else {
            CPA_COMMIT();
        }
        __syncthreads();

#pragma unroll
        for (int kk2 = 0; kk2 < 2; kk2++) {
            uint32_t Ah[2][4], Al[2][4], Bh[4][4], Bl[4][4];
#pragma unroll
            for (int mt = 0; mt < 2; mt++) {
                int ci = CIDX(arow[mt], kk2 * 2 + ac8);
                ldsm_x4(Ah[mt], aHi + ci * 16);
                ldsm_x4(Al[mt], aLo + ci * 16);
            }
#pragma unroll
            for (int nt2 = 0; nt2 < 4; nt2++) {
                int ci = CIDX(brow[nt2], kk2 * 2 + bc8);
                ldsm_x4(Bh[nt2], bHiA[par] + ci * 16);
                ldsm_x4(Bl[nt2], bLoA[par] + ci * 16);
            }
#pragma unroll
            for (int mt = 0; mt < 2; mt++)
#pragma unroll
                for (int nt = 0; nt < 8; nt++) {
                    const uint32_t* ph = &Bh[nt >> 1][(nt & 1) * 2];
                    const uint32_t* pl = &Bl[nt >> 1][(nt & 1) * 2];
                    mma16816(acc[mt][nt], Ah[mt], ph);
                    mma16816(acc[mt][nt], Ah[mt], pl);
                    mma16816(acc[mt][nt], Al[mt], ph);
                }
        }
    }

    // epilogue: fp16 activations only
    const int col0 = bn + wn + (lane & 3) * 2;
    float2 bv[8];
#pragma unroll
    for (int nt = 0; nt < 8; nt++)
        bv[nt] = *(const float2*)&bias[col0 + nt * 8];

#pragma unroll
    for (int mt = 0; mt < 2; mt++) {
        int ra = bm + wm + mt * 16 + (lane >> 2);
#pragma unroll
        for (int half = 0; half < 2; half++) {
            int r = ra + half * 8;
            if (r < M) {
                size_t rowoff = (size_t)r * 256;
#pragma unroll
                for (int nt = 0; nt < 8; nt++) {
                    float ox = acc[mt][nt][half * 2 + 0] + bv[nt].x;
                    float oy = acc[mt][nt][half * 2 + 1] + bv[nt].y;
                    *(__half2*)&g_hb[rowoff + col0 + nt * 8] =
                        __floats2half2_rn(ox, oy);
                }
            }
        }
    }
}

// ======================= GEMM (pre-split A path, triple-buffered) ===========
// smem 96KB: aHi 3x8K [0,24K) aLo [24K,48K) bHi [48K,72K) bLo [72K,96K)
template <int RELU, int STATS, int TSPLIT>
__global__ __launch_bounds__(256, 2)
void mma_gemm_pre(const __nv_bfloat16* __restrict__ Ahi,
                  const __nv_bfloat16* __restrict__ Alo,
                  int slot, const float* __restrict__ bias,
                  float* __restrict__ C,
                  __nv_bfloat16* __restrict__ Thi,
                  __nv_bfloat16* __restrict__ Tlo, int M) {
    extern __shared__ char dsm[];
    __shared__ float scs[128], scq[128];

    const int tid  = threadIdx.x;
    const int wid  = tid >> 5, lane = tid & 31;
    const int bm   = blockIdx.y * 128;
    const int bn   = blockIdx.x * 128;
    const int wm   = (wid & 3) * 32;
    const int wn   = (wid >> 2) * 64;
    const int nChunks = 8;   // K = 256

    if (STATS) {
        if (tid < 128) { scs[tid] = 0.f; scq[tid] = 0.f; }
    }

    const uint32_t sb = smem_to_u32(dsm);
    const uint32_t aHiA[3] = { sb,          sb + 8192,  sb + 16384 };
    const uint32_t aLoA[3] = { sb + 24576,  sb + 32768, sb + 40960 };
    const uint32_t bHiA[3] = { sb + 49152,  sb + 57344, sb + 65536 };
    const uint32_t bLoA[3] = { sb + 73728,  sb + 81920, sb + 90112 };

    int arow[2];
    arow[0] = wm + (lane & 15);
    arow[1] = wm + 16 + (lane & 15);
    const int ac8 = lane >> 4;
    int brow[4];
#pragma unroll
    for (int nt2 = 0; nt2 < 4; nt2++)
        brow[nt2] = wn + nt2 * 16 + (lane >> 4) * 8 + (lane & 7);
    const int bc8 = (lane >> 3) & 1;

    float acc[2][8][4];
#pragma unroll
    for (int mt = 0; mt < 2; mt++)
#pragma unroll
        for (int nt = 0; nt < 8; nt++)
#pragma unroll
            for (int i = 0; i < 4; i++) acc[mt][nt][i] = 0.f;

    const uint4* asrc_hi = (const uint4*)Ahi + (size_t)blockIdx.y * 4096;
    const uint4* asrc_lo = (const uint4*)Alo + (size_t)blockIdx.y * 4096;
    const uint4* bsrc_hi = (const uint4*)(g_Bhi + (size_t)slot * 65536
                                          + (size_t)blockIdx.x * 8 * 4096);
    const uint4* bsrc_lo = (const uint4*)(g_Blo + (size_t)slot * 65536
                                          + (size_t)blockIdx.x * 8 * 4096);

#define LOAD_CHUNK(cc, buf)                                                    \
    do {                                                                       \
        const uint4* ah = asrc_hi + (size_t)(cc) * 512;                        \
        const uint4* al = asrc_lo + (size_t)(cc) * 512;                        \
        const uint4* bh = bsrc_hi + (size_t)(cc) * 512;                        \
        const uint4* bl = bsrc_lo + (size_t)(cc) * 512;                        \
        cpa16(aHiA[buf] + tid * 16,        ah + tid);                          \
        cpa16(aHiA[buf] + tid * 16 + 4096, ah + tid + 256);                    \
        cpa16(aLoA[buf] + tid * 16,        al + tid);                          \
        cpa16(aLoA[buf] + tid * 16 + 4096, al + tid + 256);                    \
        cpa16(bHiA[buf] + tid * 16,        bh + tid);                          \
        cpa16(bHiA[buf] + tid * 16 + 4096, bh + tid + 256);                    \
        cpa16(bLoA[buf] + tid * 16,        bl + tid);                          \
        cpa16(bLoA[buf] + tid * 16 + 4096, bl + tid + 256);                    \
        CPA_COMMIT();                                                          \
    } while (0)

    LOAD_CHUNK(0, 0);
    LOAD_CHUNK(1, 1);

    for (int c = 0; c < nChunks; c++) {
        const int par = c % 3;
        CPA_WAIT1();        // chunk c complete (c+1 may still be in flight)
        __syncthreads();    // visibility + MMA(c-1) done with buffer (c+2)%3

        if (c + 2 < nChunks) LOAD_CHUNK(c + 2, (c + 2) % 3);
        else CPA_COMMIT();   // keep group-count parity

#pragma unroll
        for (int kk2 = 0; kk2 < 2; kk2++) {
            uint32_t Ah[2][4], Al[2][4], Bh[4][4], Bl[4][4];
#pragma unroll
            for (int mt = 0; mt < 2; mt++) {
                int ci = CIDX(arow[mt], kk2 * 2 + ac8);
                ldsm_x4(Ah[mt], aHiA[par] + ci * 16);
                ldsm_x4(Al[mt], aLoA[par] + ci * 16);
            }
#pragma unroll
            for (int nt2 = 0; nt2 < 4; nt2++) {
                int ci = CIDX(brow[nt2], kk2 * 2 + bc8);
                ldsm_x4(Bh[nt2], bHiA[par] + ci * 16);
                ldsm_x4(Bl[nt2], bLoA[par] + ci * 16);
            }
#pragma unroll
            for (int mt = 0; mt < 2; mt++)
#pragma unroll
                for (int nt = 0; nt < 8; nt++) {
                    const uint32_t* ph = &Bh[nt >> 1][(nt & 1) * 2];
                    const uint32_t* pl = &Bl[nt >> 1][(nt & 1) * 2];
                    mma16816(acc[mt][nt], Ah[mt], ph);
                    mma16816(acc[mt][nt], Ah[mt], pl);
                    mma16816(acc[mt][nt], Al[mt], ph);
                }
        }
    }
#undef LOAD_CHUNK

    // ---- epilogue ----
    const int col0 = bn + wn + (lane & 3) * 2;
    float2 bv[8];
#pragma unroll
    for (int nt = 0; nt < 8; nt++)
        bv[nt] = *(const float2*)&bias[col0 + nt * 8];

    float s_c[8][2], q_c[8][2];
    if (STATS) {
#pragma unroll
        for (int nt = 0; nt < 8; nt++) {
            s_c[nt][0] = s_c[nt][1] = 0.f;
            q_c[nt][0] = q_c[nt][1] = 0.f;
        }
    }

#pragma unroll
    for (int mt = 0; mt < 2; mt++) {
#pragma unroll
        for (int half = 0; half < 2; half++) {
            int rr = wm + mt * 16 + (lane >> 2) + half * 8;
            int r  = bm + rr;
            if (r < M) {
                size_t rowoff = (size_t)r * 256;
#pragma unroll
                for (int nt = 0; nt < 8; nt++) {
                    float2 o;
                    o.x = acc[mt][nt][half * 2 + 0] + bv[nt].x;
                    o.y = acc[mt][nt][half * 2 + 1] + bv[nt].y;
                    if (RELU) { o.x = fmaxf(o.x, 0.f); o.y = fmaxf(o.y, 0.f); }
                    if (STATS) {
                        s_c[nt][0] += o.x;          s_c[nt][1] += o.y;
                        q_c[nt][0] = fmaf(o.x, o.x, q_c[nt][0]);
                        q_c[nt][1] = fmaf(o.y, o.y, q_c[nt][1]);
                    }
                    if (TSPLIT) {
                        int colg = col0 + nt * 8;
                        int kc = colg >> 5;
                        int c8 = (colg >> 3) & 3;
                        size_t ch = ((size_t)blockIdx.y * 8 + kc) * 512
                                  + CIDX(rr, c8);
                        uint32_t hb, lb;
                        split2(o.x, o.y, hb, lb);
                        *(uint32_t*)((char*)Thi + ch * 16 + (lane & 3) * 4) = hb;
                        *(uint32_t*)((char*)Tlo + ch * 16 + (lane & 3) * 4) = lb;
                    } else {
                        *(float2*)&C[rowoff + col0 + nt * 8] = o;
                    }
                }
            }
        }
    }

    if (STATS) {
        const int cb = wn + (lane & 3) * 2;
#pragma unroll
        for (int nt = 0; nt < 8; nt++) {
            atomicAdd(&scs[cb + nt * 8],     s_c[nt][0]);
            atomicAdd(&scs[cb + nt * 8 + 1], s_c[nt][1]);
            atomicAdd(&scq[cb + nt * 8],     q_c[nt][0]);
            atomicAdd(&scq[cb + nt * 8 + 1], q_c[nt][1]);
        }
        __syncthreads();
        if (tid < 128) {
            atomicAdd(&g_colsum[bn + tid], scs[tid]);
            atomicAdd(&g_colsq[bn + tid],  scq[tid]);
        }
    }
}

// ======================= BN finalize (self-resetting) =======================
__global__ void finalize_stats_kernel(const float* __restrict__ gamma,
                                      const float* __restrict__ beta) {
    int c = threadIdx.x;
    float mean = g_colsum[c] * (1.0f / NN);
    float var  = g_colsq[c] * (1.0f / NN) - mean * mean;
    float sc   = gamma[c] * rsqrtf(var + BN_EPS);
    g_scale[c] = sc;
    g_shift[c] = beta[c] - mean * sc;
    g_colsum[c] = 0.f;
    g_colsq[c]  = 0.f;
}

// ======================= BN apply + ReLU + pool (fp16 out) ==================
__global__ __launch_bounds__(256)
void bn_apply_kernel(const int* __restrict__ batch, int layer) {
    int row = blockIdx.x * 4 + (threadIdx.x >> 6);
    if (row >= NN) return;
    int c4 = (threadIdx.x & 63) * 4;
    float4 v  = *(const float4*)&g_z[(size_t)row * DD + c4];
    float4 sc = *(const float4*)&g_scale[c4];
    float4 sh = *(const float4*)&g_shift[c4];
    float4 o;
    o.x = fmaxf(fmaf(v.x, sc.x, sh.x), 0.f);
    o.y = fmaxf(fmaf(v.y, sc.y, sh.y), 0.f);
    o.z = fmaxf(fmaf(v.z, sc.z, sh.z), 0.f);
    o.w = fmaxf(fmaf(v.w, sc.w, sh.w), 0.f);
    size_t off = (size_t)row * DD + c4;
    *(__half2*)&g_hb[off]     = __floats2half2_rn(o.x, o.y);
    *(__half2*)&g_hb[off + 2] = __floats2half2_rn(o.z, o.w);
    int gidx = batch[row];
    red_add_v4(&g_pooled[(size_t)gidx * (DD * LL) + layer * DD + c4], o);
}

// ======================= MLP head ===========================================
__global__ __launch_bounds__(128)
void fc1_kernel(const float* __restrict__ W, const float* __restrict__ b) {
    int row = blockIdx.x;
    int j   = threadIdx.x;
    __shared__ float sp[DD * LL];
    for (int k = j; k < DD * LL; k += 128)
        sp[k] = g_pooled[(size_t)row * (DD * LL) + k];
    __syncthreads();
    float inv = 1.0f / fmaxf(g_cnt[row], 1.0f);
    float s = 0.f;
#pragma unroll 8
    for (int k = 0; k < DD * LL; k++)
        s = fmaf(sp[k], W[(size_t)k * 128 + j], s);
    g_hid[(size_t)row * 128 + j] = fmaxf(fmaf(s, inv, b[j]), 0.f);
}

__global__ __launch_bounds__(128)
void fc2_kernel(const float* __restrict__ W, const float* __restrict__ b,
                float* __restrict__ out) {
    int row = blockIdx.x;
    int t   = threadIdx.x;
    float v = g_hid[(size_t)row * 128 + t] * W[t];
#pragma unroll
    for (int off = 16; off; off >>= 1)
        v += __shfl_down_sync(0xFFFFFFFFu, v, off);
    __shared__ float ws[4];
    if ((t & 31) == 0) ws[t >> 5] = v;
    __syncthreads();
    if (t == 0) out[row] = ws[0] + ws[1] + ws[2] + ws[3] + b[0];
}

// ======================= launch ============================================
extern "C" void kernel_launch(void* const* d_in, const int* in_sizes, int n_in,
                              void* d_out, int out_size) {
    const float* x     = (const float*)d_in[0];
    const int*   ei    = (const int*)d_in[1];
    const int*   batch = (const int*)d_in[2];
    int base = n_in - 12;
    const float* W_enc = (const float*)d_in[base + 0];
    const float* b_enc = (const float*)d_in[base + 1];
    const float* W1    = (const float*)d_in[base + 2];
    const float* b1    = (const float*)d_in[base + 3];
    const float* W2    = (const float*)d_in[base + 4];
    const float* b2    = (const float*)d_in[base + 5];
    const float* gamma = (const float*)d_in[base + 6];
    const float* beta  = (const float*)d_in[base + 7];
    const float* Wf1   = (const float*)d_in[base + 8];
    const float* bf1   = (const float*)d_in[base + 9];
    const float* Wf2   = (const float*)d_in[base + 10];
    const float* bf2   = (const float*)d_in[base + 11];
    float* out = (float*)d_out;

    float* pz = nullptr;
    __nv_bfloat16 *pAhi = nullptr, *pAlo = nullptr, *pThi = nullptr, *pTlo = nullptr;
    cudaGetSymbolAddress((void**)&pz, g_z);
    cudaGetSymbolAddress((void**)&pAhi, g_Ahi);
    cudaGetSymbolAddress((void**)&pAlo, g_Alo);
    cudaGetSymbolAddress((void**)&pThi, g_Thi);
    cudaGetSymbolAddress((void**)&pTlo, g_Tlo);

    const int SMB_CONV = 49152;
    const int SMB_PRE  = 98304;
    cudaFuncSetAttribute(mma_gemm_conv,
                         cudaFuncAttributeMaxDynamicSharedMemorySize, SMB_CONV);
    cudaFuncSetAttribute(mma_gemm_pre<1, 0, 1>,
                         cudaFuncAttributeMaxDynamicSharedMemorySize, SMB_PRE);
    cudaFuncSetAttribute(mma_gemm_pre<0, 1, 0>,
                         cudaFuncAttributeMaxDynamicSharedMemorySize, SMB_PRE);

    dim3 ge(2, (NN + 127) / 128);   // (nblk, 391)

    prep_all_weights_kernel<<<(FIN * 256 + 6 * DD * 256 + 255) / 256, 256>>>(
        W_enc, W1, W2);
    zero_setup_kernel<<<(GG * DD * LL + 255) / 256, 256>>>();
    hist_count_kernel<<<(EE + 255) / 256, 256>>>(ei, batch);
    mma_gemm_conv<<<ge, 256, SMB_CONV>>>(x, FIN, 0, b_enc, NN);
    scan_kernel<<<1, 1024>>>();
    fill_kernel<<<(EE + 255) / 256, 256>>>(ei);

    for (int l = 0; l < LL; l++) {
        gather_kernel<<<(NN + 7) / 8, 256>>>();   // g_hb -> g_Ahi/g_Alo
        mma_gemm_pre<1, 0, 1><<<ge, 256, SMB_PRE>>>(
            pAhi, pAlo, 1 + l, b1 + l * DD, pz, pThi, pTlo, NN);
        mma_gemm_pre<0, 1, 0><<<ge, 256, SMB_PRE>>>(
            pThi, pTlo, 4 + l, b2 + l * DD, pz, pThi, pTlo, NN);
        finalize_stats_kernel<<<1, DD>>>(gamma + l * DD, beta + l * DD);
        bn_apply_kernel<<<NN / 4, 256>>>(batch, l);
    }

    fc1_kernel<<<GG, 128>>>(Wf1, bf1);
    fc2_kernel<<<GG, 128>>>(Wf2, bf2, out);
    (void)in_sizes; (void)out_size;
}